// round 9
// baseline (speedup 1.0000x reference)
#include <cuda_runtime.h>
#include <cuda_fp16.h>
#include <cstdint>

#define D_MODEL   1024
#define NUM_HEADS 16
#define D_HEAD    64
#define BATCH     4
#define SEQ       2048
#define MTOT      (BATCH * SEQ)   // 8192
#define QKV_EL    (BATCH * NUM_HEADS * SEQ * D_HEAD)   // 8388608

// ---------------- scratch (device globals: allocation-guard safe) ----------
__device__ __half g_xh[MTOT * D_MODEL],  g_xl[MTOT * D_MODEL];
__device__ __half g_wh[4][D_MODEL * D_MODEL], g_wl[4][D_MODEL * D_MODEL];
__device__ __half g_qh[QKV_EL], g_ql[QKV_EL];          // [b,h,s,d]
__device__ __half g_kh[QKV_EL], g_kl[QKV_EL];          // [b,h,s,d]
__device__ __half g_vth[QKV_EL], g_vtl[QKV_EL];        // [b,h,d,s]
__device__ __half g_ch[MTOT * D_MODEL], g_cl[MTOT * D_MODEL];   // ctx

// ---------------- helpers ----------------------------------------------------
__device__ __forceinline__ void split_hf(float x, __half& h, __half& l) {
    h = __float2half_rn(x);
    l = __float2half_rn(x - __half2float(h));
}
__device__ __forceinline__ unsigned pk(__half a, __half b) {
    return (unsigned)__half_as_ushort(a) | ((unsigned)__half_as_ushort(b) << 16);
}
__device__ __forceinline__ void split_store4(float4 v, __half* hp, __half* lp) {
    __half h0, l0, h1, l1, h2, l2, h3, l3;
    split_hf(v.x, h0, l0); split_hf(v.y, h1, l1);
    split_hf(v.z, h2, l2); split_hf(v.w, h3, l3);
    *(uint2*)hp = make_uint2(pk(h0, h1), pk(h2, h3));
    *(uint2*)lp = make_uint2(pk(l0, l1), pk(l2, l3));
}
// fp32-accumulator mma (fp16 inputs)
__device__ __forceinline__ void mmaF(float* c, const unsigned* a, unsigned b0, unsigned b1) {
    asm volatile(
        "mma.sync.aligned.m16n8k16.row.col.f32.f16.f16.f32 "
        "{%0,%1,%2,%3}, {%4,%5,%6,%7}, {%8,%9}, {%0,%1,%2,%3};"
        : "+f"(c[0]), "+f"(c[1]), "+f"(c[2]), "+f"(c[3])
        : "r"(a[0]), "r"(a[1]), "r"(a[2]), "r"(a[3]), "r"(b0), "r"(b1));
}
// fp16-accumulator mma, fresh accumulator (C = 0)
__device__ __forceinline__ void mmaH0(unsigned* c, const unsigned* a, unsigned b0, unsigned b1) {
    asm volatile(
        "mma.sync.aligned.m16n8k16.row.col.f16.f16.f16.f16 "
        "{%0,%1}, {%2,%3,%4,%5}, {%6,%7}, {%8,%9};"
        : "=r"(c[0]), "=r"(c[1])
        : "r"(a[0]), "r"(a[1]), "r"(a[2]), "r"(a[3]), "r"(b0), "r"(b1),
          "r"(0u), "r"(0u));
}
// fp16-accumulator mma, accumulate
__device__ __forceinline__ void mmaH(unsigned* c, const unsigned* a, unsigned b0, unsigned b1) {
    asm volatile(
        "mma.sync.aligned.m16n8k16.row.col.f16.f16.f16.f16 "
        "{%0,%1}, {%2,%3,%4,%5}, {%6,%7}, {%0,%1};"
        : "+r"(c[0]), "+r"(c[1])
        : "r"(a[0]), "r"(a[1]), "r"(a[2]), "r"(a[3]), "r"(b0), "r"(b1));
}
// fold an f16x2-pair accumulator into the fp32 accumulator
__device__ __forceinline__ void foldcc(float* c, const unsigned* cc) {
    float2 lo = __half22float2(*(const __half2*)&cc[0]);
    float2 hi = __half22float2(*(const __half2*)&cc[1]);
    c[0] += lo.x; c[1] += lo.y; c[2] += hi.x; c[3] += hi.y;
}
__device__ __forceinline__ void ldsm4(unsigned r[4], const __half* p) {
    unsigned a = (unsigned)__cvta_generic_to_shared(p);
    asm volatile("ldmatrix.sync.aligned.m8n8.x4.shared.b16 {%0,%1,%2,%3}, [%4];"
                 : "=r"(r[0]), "=r"(r[1]), "=r"(r[2]), "=r"(r[3]) : "r"(a));
}
__device__ __forceinline__ void cp16(__half* s, const __half* g) {
    unsigned sa = (unsigned)__cvta_generic_to_shared(s);
    asm volatile("cp.async.cg.shared.global [%0], [%1], 16;" :: "r"(sa), "l"(g));
}
#define CP_COMMIT() asm volatile("cp.async.commit_group;")
#define CP_WAIT0()  asm volatile("cp.async.wait_group 0;")
#define CP_WAIT1()  asm volatile("cp.async.wait_group 1;")

// fast exp2 on the FMA pipe (MUFU-free)
__device__ __forceinline__ float exp2_fast(float y) {
    y = fmaxf(y, -120.f);
    float z = y + 12582912.f;
    int   e = __float_as_int(z);
    float f = y - (z - 12582912.f);
    float p = 1.f + f * (0.6931471805599453f + f * (0.2402265069591007f +
              f * (0.0555041086648216f + f * (0.0096181291076285f +
              f * 0.0013333558146429f))));
    return __int_as_float(__float_as_int(p) + (e << 23));
}
#define SCALE_LOG2E 0.18033688011112042f   // 0.125 * log2(e)

// ---------------- one-shot split of x + weights ------------------------------
__global__ __launch_bounds__(256) void split_all(const float* __restrict__ x,
                                                 const float* __restrict__ Qw,
                                                 const float* __restrict__ Kw,
                                                 const float* __restrict__ Vw,
                                                 const float* __restrict__ Ow)
{
    const int idx = blockIdx.x * 256 + threadIdx.x;        // one float4 each
    const float* src;
    __half *hp, *lp;
    size_t off;
    if (idx < 2097152) {
        src = x; off = idx; hp = g_xh; lp = g_xl;
    } else {
        const int w = (idx - 2097152) >> 18;
        off = (size_t)((idx - 2097152) & 262143);
        src = (w == 0) ? Qw : (w == 1) ? Kw : (w == 2) ? Vw : Ow;
        hp = g_wh[w]; lp = g_wl[w];
    }
    float4 v = ((const float4*)src)[off];
    split_store4(v, hp + off * 4, lp + off * 4);
}

// ---------------- split-fp16 GEMM, cp.async + ldmatrix -----------------------
// Block tile 128x128, BK=32, 256 threads = 8 warps (4m x 2n), warp tile 32x64.
// Per 16-k step: hi*hi in f32-acc; (lo*hi + hi*lo) chained in f16-acc, folded.
#define SSTR 40
#define GBUF (128 * SSTR)
#define GSTG (4 * GBUF)
#define GEMM_SMEM (2 * GSTG * 2)      // 81920 bytes

__device__ __forceinline__ void gemm_hf_body(const __half* __restrict__ Agh,
                                             const __half* __restrict__ Agl,
                                             const __half* __restrict__ Bgh,
                                             const __half* __restrict__ Bgl,
                                             int m0, int n0,
                                             float (&c)[2][8][4],
                                             __half* sm)
{
    const int tid  = threadIdx.x;
    const int lane = tid & 31;
    const int warp = tid >> 5;
    const int wm   = (warp >> 1) * 32;
    const int wn   = (warp & 1) * 64;
    const int lrow = tid >> 1;
    const int lcol = (tid & 1) * 16;
    const int so   = lrow * SSTR + lcol;

    const int aoff = ((lane & 7) + ((lane >> 3) & 1) * 8) * SSTR + (lane >> 4) * 8;
    const int boff = ((lane & 7) + (lane >> 4) * 8) * SSTR + ((lane >> 3) & 1) * 8;

    const size_t arow = (size_t)(m0 + lrow) * D_MODEL + lcol;
    const size_t brow = (size_t)(n0 + lrow) * D_MODEL + lcol;

    {   // prologue: stage 0 <- k-tile 0
        __half* st = sm;
        cp16(st + so,            Agh + arow); cp16(st + so + 8,            Agh + arow + 8);
        cp16(st + GBUF + so,     Agl + arow); cp16(st + GBUF + so + 8,     Agl + arow + 8);
        cp16(st + 2 * GBUF + so, Bgh + brow); cp16(st + 2 * GBUF + so + 8, Bgh + brow + 8);
        cp16(st + 3 * GBUF + so, Bgl + brow); cp16(st + 3 * GBUF + so + 8, Bgl + brow + 8);
        CP_COMMIT();
        CP_WAIT0();
    }
    __syncthreads();

    for (int kt = 0; kt < 32; kt++) {
        if (kt + 1 < 32) {
            __half* nx = sm + ((kt + 1) & 1) * GSTG;
            const int k0 = (kt + 1) * 32;
            cp16(nx + so,            Agh + arow + k0); cp16(nx + so + 8,            Agh + arow + k0 + 8);
            cp16(nx + GBUF + so,     Agl + arow + k0); cp16(nx + GBUF + so + 8,     Agl + arow + k0 + 8);
            cp16(nx + 2 * GBUF + so, Bgh + brow + k0); cp16(nx + 2 * GBUF + so + 8, Bgh + brow + k0 + 8);
            cp16(nx + 3 * GBUF + so, Bgl + brow + k0); cp16(nx + 3 * GBUF + so + 8, Bgl + brow + k0 + 8);
            CP_COMMIT();
        }

        const __half* Ah = sm + (kt & 1) * GSTG;
        const __half* Al = Ah + GBUF;
        const __half* Bh = Ah + 2 * GBUF;
        const __half* Bl = Ah + 3 * GBUF;

        #pragma unroll
        for (int ks = 0; ks < 2; ks++) {
            const int kk = ks * 16;
            unsigned ahi[2][4], alo[2][4];
            ldsm4(ahi[0], Ah + (wm     ) * SSTR + kk + aoff);
            ldsm4(ahi[1], Ah + (wm + 16) * SSTR + kk + aoff);
            ldsm4(alo[0], Al + (wm     ) * SSTR + kk + aoff);
            ldsm4(alo[1], Al + (wm + 16) * SSTR + kk + aoff);
            #pragma unroll
            for (int p = 0; p < 2; p++) {
                unsigned bh0[4], bl0[4], bh1[4], bl1[4];
                ldsm4(bh0, Bh + (wn + 32 * p     ) * SSTR + kk + boff);
                ldsm4(bl0, Bl + (wn + 32 * p     ) * SSTR + kk + boff);
                ldsm4(bh1, Bh + (wn + 32 * p + 16) * SSTR + kk + boff);
                ldsm4(bl1, Bl + (wn + 32 * p + 16) * SSTR + kk + boff);
                const int j0 = 4 * p;
                // ---- main term hi*hi (f32 acc) ----
                mmaF(c[0][j0 + 0], ahi[0], bh0[0], bh0[1]);
                mmaF(c[1][j0 + 0], ahi[1], bh0[0], bh0[1]);
                mmaF(c[0][j0 + 1], ahi[0], bh0[2], bh0[3]);
                mmaF(c[1][j0 + 1], ahi[1], bh0[2], bh0[3]);
                mmaF(c[0][j0 + 2], ahi[0], bh1[0], bh1[1]);
                mmaF(c[1][j0 + 2], ahi[1], bh1[0], bh1[1]);
                mmaF(c[0][j0 + 3], ahi[0], bh1[2], bh1[3]);
                mmaF(c[1][j0 + 3], ahi[1], bh1[2], bh1[3]);
                // ---- correction terms lo*hi + hi*lo (f16 acc), then fold ----
                unsigned cc[2][4][2];
                #pragma unroll
                for (int i = 0; i < 2; i++) {
                    mmaH0(cc[i][0], alo[i], bh0[0], bh0[1]);
                    mmaH0(cc[i][1], alo[i], bh0[2], bh0[3]);
                    mmaH0(cc[i][2], alo[i], bh1[0], bh1[1]);
                    mmaH0(cc[i][3], alo[i], bh1[2], bh1[3]);
                    mmaH(cc[i][0], ahi[i], bl0[0], bl0[1]);
                    mmaH(cc[i][1], ahi[i], bl0[2], bl0[3]);
                    mmaH(cc[i][2], ahi[i], bl1[0], bl1[1]);
                    mmaH(cc[i][3], ahi[i], bl1[2], bl1[3]);
                }
                #pragma unroll
                for (int i = 0; i < 2; i++)
                    #pragma unroll
                    for (int jj = 0; jj < 4; jj++)
                        foldcc(c[i][j0 + jj], cc[i][jj]);
            }
        }
        CP_WAIT0();
        __syncthreads();
    }
}

// Fused QKV projection; blockIdx.z selects weight.
__global__ __launch_bounds__(256, 2) void gemm_qkv()
{
    extern __shared__ __half smg[];
    float c[2][8][4];
    #pragma unroll
    for (int i = 0; i < 2; i++)
        #pragma unroll
        for (int j = 0; j < 8; j++)
            #pragma unroll
            for (int q = 0; q < 4; q++) c[i][j][q] = 0.f;

    const int m0 = blockIdx.y * 128;
    const int n0 = blockIdx.x * 128;
    const int z  = blockIdx.z;

    gemm_hf_body(g_xh, g_xl, g_wh[z], g_wl[z], m0, n0, c, smg);

    const int lane = threadIdx.x & 31;
    const int g = lane >> 2, t = lane & 3;
    const int warp = threadIdx.x >> 5;
    const int wm = (warp >> 1) * 32, wn = (warp & 1) * 64;

    #pragma unroll
    for (int i = 0; i < 2; i++) {
        #pragma unroll
        for (int j = 0; j < 8; j++) {
            const int n = n0 + wn + 8 * j + 2 * t;
            const int h = n >> 6, d = n & 63;
            const int r0 = m0 + wm + 16 * i + g;
            const int r1 = r0 + 8;
            const int b0 = r0 >> 11, s0 = r0 & 2047;
            const int b1 = r1 >> 11, s1 = r1 & 2047;
            __half h0, l0, h1, l1, h2, l2, h3, l3;
            split_hf(c[i][j][0], h0, l0); split_hf(c[i][j][1], h1, l1);
            split_hf(c[i][j][2], h2, l2); split_hf(c[i][j][3], h3, l3);
            if (z == 2) {
                const size_t v0 = ((size_t)(b0 * NUM_HEADS + h) * D_HEAD + d) * SEQ + s0;
                const size_t v1 = ((size_t)(b1 * NUM_HEADS + h) * D_HEAD + d) * SEQ + s1;
                g_vth[v0] = h0; g_vtl[v0] = l0;
                g_vth[v0 + SEQ] = h1; g_vtl[v0 + SEQ] = l1;
                g_vth[v1] = h2; g_vtl[v1] = l2;
                g_vth[v1 + SEQ] = h3; g_vtl[v1 + SEQ] = l3;
            } else {
                __half* dh = (z == 0) ? g_qh : g_kh;
                __half* dl = (z == 0) ? g_ql : g_kl;
                const size_t i0 = ((size_t)(b0 * NUM_HEADS + h) * SEQ + s0) * D_HEAD + d;
                const size_t i1 = ((size_t)(b1 * NUM_HEADS + h) * SEQ + s1) * D_HEAD + d;
                *(unsigned*)&dh[i0] = pk(h0, h1);
                *(unsigned*)&dl[i0] = pk(l0, l1);
                *(unsigned*)&dh[i1] = pk(h2, h3);
                *(unsigned*)&dl[i1] = pk(l2, l3);
            }
        }
    }
}

// Output projection: out = ctx @ Ow^T, fp32 out.
__global__ __launch_bounds__(256, 2) void gemm_out(float* __restrict__ out)
{
    extern __shared__ __half smg[];
    float c[2][8][4];
    #pragma unroll
    for (int i = 0; i < 2; i++)
        #pragma unroll
        for (int j = 0; j < 8; j++)
            #pragma unroll
            for (int q = 0; q < 4; q++) c[i][j][q] = 0.f;

    const int m0 = blockIdx.y * 128;
    const int n0 = blockIdx.x * 128;

    gemm_hf_body(g_ch, g_cl, g_wh[3], g_wl[3], m0, n0, c, smg);

    const int lane = threadIdx.x & 31;
    const int g = lane >> 2, t = lane & 3;
    const int warp = threadIdx.x >> 5;
    const int wm = (warp >> 1) * 32, wn = (warp & 1) * 64;

    #pragma unroll
    for (int i = 0; i < 2; i++) {
        #pragma unroll
        for (int j = 0; j < 8; j++) {
            const int n  = n0 + wn + 8 * j + 2 * t;
            const int r0 = m0 + wm + 16 * i + g;
            *(float2*)&out[(size_t)r0 * D_MODEL + n] = make_float2(c[i][j][0], c[i][j][1]);
            *(float2*)&out[(size_t)(r0 + 8) * D_MODEL + n] = make_float2(c[i][j][2], c[i][j][3]);
        }
    }
}

// ---------------- Flash attention: Q-in-regs, KV double-buffer, ldmatrix -----
// Same split scheme: hi*hi f32-acc, corrections f16-acc folded per group.
#define QSTR 72
#define TILEC (64 * QSTR)
#define ATTN_SMEM (12 * TILEC * 2)        // 110592 bytes

__global__ __launch_bounds__(256, 2) void attn_mma(const unsigned char* __restrict__ pm)
{
    extern __shared__ __half smb[];
    __half* stg0 = smb;
    __half* stg1 = smb + 4 * TILEC;
    __half* Ph   = smb + 8 * TILEC;
    __half* Pl   = smb + 10 * TILEC;

    const int qt = gridDim.x - 1 - blockIdx.x;
    const int h  = blockIdx.y;
    const int b  = blockIdx.z;
    const int tid  = threadIdx.x;
    const int lane = tid & 31;
    const int warp = tid >> 5;
    const int g = lane >> 2, t = lane & 3;
    const size_t base = (size_t)(b * NUM_HEADS + h) * SEQ;

    const int rw = warp * 16;
    const int Rg = qt * 128 + rw;
    const int kt_max = 2 * qt + 1;

    const int aoffQ = ((lane & 7) + ((lane >> 3) & 1) * 8) * QSTR + (lane >> 4) * 8;
    const int boffQ = ((lane & 7) + (lane >> 4) * 8) * QSTR + ((lane >> 3) & 1) * 8;

    const int krow = tid >> 2;
    const int kcs  = (tid & 3) * 16;
    const int kso  = krow * QSTR + kcs;
    const size_t vbase = ((size_t)(b * NUM_HEADS + h) * D_HEAD + krow) * SEQ + kcs;
    const size_t kbase = (base + krow) * D_HEAD + kcs;

    {
        const int row = tid >> 1, cs = (tid & 1) * 32;
        const size_t ga = (base + (size_t)qt * 128 + row) * D_HEAD + cs;
        const int so = row * QSTR + cs;
        __half* Qsh = stg1;
        __half* Qsl = stg1 + 2 * TILEC;
        #pragma unroll
        for (int u = 0; u < 4; u++) {
            cp16(&Qsh[so + 8 * u], &g_qh[ga + 8 * u]);
            cp16(&Qsl[so + 8 * u], &g_ql[ga + 8 * u]);
        }
        CP_COMMIT();
    }
    {
        cp16(&stg0[kso],             &g_kh[kbase]); cp16(&stg0[kso + 8],             &g_kh[kbase + 8]);
        cp16(&stg0[TILEC + kso],     &g_kl[kbase]); cp16(&stg0[TILEC + kso + 8],     &g_kl[kbase + 8]);
        cp16(&stg0[2 * TILEC + kso], &g_vth[vbase]); cp16(&stg0[2 * TILEC + kso + 8], &g_vth[vbase + 8]);
        cp16(&stg0[3 * TILEC + kso], &g_vtl[vbase]); cp16(&stg0[3 * TILEC + kso + 8], &g_vtl[vbase + 8]);
        CP_COMMIT();
    }
    CP_WAIT1();
    __syncthreads();

    unsigned qh[4][4], ql[4][4];
    #pragma unroll
    for (int ks = 0; ks < 4; ks++) {
        ldsm4(qh[ks], stg1 + rw * QSTR + 16 * ks + aoffQ);
        ldsm4(ql[ks], stg1 + 2 * TILEC + rw * QSTR + 16 * ks + aoffQ);
    }
    __syncthreads();

    float o[8][4];
    float m_i[2] = {-1e30f, -1e30f};
    float l_i[2] = {0.f, 0.f};
    #pragma unroll
    for (int j = 0; j < 8; j++)
        #pragma unroll
        for (int q = 0; q < 4; q++) o[j][q] = 0.f;

    for (int kt = 0; kt <= kt_max; kt++) {
        if (kt < kt_max) {
            __half* nx = ((kt + 1) & 1) ? stg1 : stg0;
            const size_t gk = kbase + (size_t)(kt + 1) * 64 * D_HEAD;
            const size_t gv = vbase + (size_t)(kt + 1) * 64;
            cp16(&nx[kso],             &g_kh[gk]);  cp16(&nx[kso + 8],             &g_kh[gk + 8]);
            cp16(&nx[TILEC + kso],     &g_kl[gk]);  cp16(&nx[TILEC + kso + 8],     &g_kl[gk + 8]);
            cp16(&nx[2 * TILEC + kso], &g_vth[gv]); cp16(&nx[2 * TILEC + kso + 8], &g_vth[gv + 8]);
            cp16(&nx[3 * TILEC + kso], &g_vtl[gv]); cp16(&nx[3 * TILEC + kso + 8], &g_vtl[gv + 8]);
            CP_COMMIT();
            CP_WAIT1();
        } else {
            CP_WAIT0();
        }
        __syncthreads();

        const int C0 = kt * 64;
        if (C0 <= Rg + 15) {
            const __half* Kh = (kt & 1) ? stg1 : stg0;
            const __half* Kl = Kh + TILEC;
            const __half* Vh = Kh + 2 * TILEC;
            const __half* Vl = Kh + 3 * TILEC;

            float s[8][4];
            #pragma unroll
            for (int j = 0; j < 8; j++)
                #pragma unroll
                for (int q = 0; q < 4; q++) s[j][q] = 0.f;

            // ---- S = Q @ K^T ----
            #pragma unroll
            for (int ks = 0; ks < 4; ks++) {
                const int kk = 16 * ks;
                #pragma unroll
                for (int p = 0; p < 2; p++) {
                    unsigned bh0[4], bl0[4], bh1[4], bl1[4];
                    ldsm4(bh0, Kh + (32 * p     ) * QSTR + kk + boffQ);
                    ldsm4(bl0, Kl + (32 * p     ) * QSTR + kk + boffQ);
                    ldsm4(bh1, Kh + (32 * p + 16) * QSTR + kk + boffQ);
                    ldsm4(bl1, Kl + (32 * p + 16) * QSTR + kk + boffQ);
                    const int j0 = 4 * p;
                    mmaF(s[j0 + 0], qh[ks], bh0[0], bh0[1]);
                    mmaF(s[j0 + 1], qh[ks], bh0[2], bh0[3]);
                    mmaF(s[j0 + 2], qh[ks], bh1[0], bh1[1]);
                    mmaF(s[j0 + 3], qh[ks], bh1[2], bh1[3]);
                    unsigned cc[4][2];
                    mmaH0(cc[0], ql[ks], bh0[0], bh0[1]);
                    mmaH0(cc[1], ql[ks], bh0[2], bh0[3]);
                    mmaH0(cc[2], ql[ks], bh1[0], bh1[1]);
                    mmaH0(cc[3], ql[ks], bh1[2], bh1[3]);
                    mmaH(cc[0], qh[ks], bl0[0], bl0[1]);
                    mmaH(cc[1], qh[ks], bl0[2], bl0[3]);
                    mmaH(cc[2], qh[ks], bl1[0], bl1[1]);
                    mmaH(cc[3], qh[ks], bl1[2], bl1[3]);
                    #pragma unroll
                    for (int jj = 0; jj < 4; jj++) foldcc(s[j0 + jj], cc[jj]);
                }
            }

            const unsigned char* pmb = pm + (size_t)b * SEQ + C0;
            const int r0 = Rg + g, r1 = r0 + 8;
            #pragma unroll
            for (int j = 0; j < 8; j++) {
                const int c0 = C0 + 8 * j + 2 * t, c1 = c0 + 1;
                const bool p0 = pmb[8 * j + 2 * t] != 0;
                const bool p1 = pmb[8 * j + 2 * t + 1] != 0;
                float v;
                v = s[j][0] * SCALE_LOG2E; if (c0 > r0 || p0) v = -1e30f; s[j][0] = v;
                v = s[j][1] * SCALE_LOG2E; if (c1 > r0 || p1) v = -1e30f; s[j][1] = v;
                v = s[j][2] * SCALE_LOG2E; if (c0 > r1 || p0) v = -1e30f; s[j][2] = v;
                v = s[j][3] * SCALE_LOG2E; if (c1 > r1 || p1) v = -1e30f; s[j][3] = v;
            }

            #pragma unroll
            for (int rr = 0; rr < 2; rr++) {
                float rm = -1e30f;
                #pragma unroll
                for (int j = 0; j < 8; j++)
                    rm = fmaxf(rm, fmaxf(s[j][2 * rr], s[j][2 * rr + 1]));
                rm = fmaxf(rm, __shfl_xor_sync(0xffffffffu, rm, 1));
                rm = fmaxf(rm, __shfl_xor_sync(0xffffffffu, rm, 2));
                const float mn    = fmaxf(m_i[rr], rm);
                const float alpha = exp2_fast(m_i[rr] - mn);
                m_i[rr] = mn;
                float rs = 0.f;
                #pragma unroll
                for (int j = 0; j < 8; j++) {
                    s[j][2 * rr    ] = exp2_fast(s[j][2 * rr    ] - mn);
                    s[j][2 * rr + 1] = exp2_fast(s[j][2 * rr + 1] - mn);
                    rs += s[j][2 * rr] + s[j][2 * rr + 1];
                }
                rs += __shfl_xor_sync(0xffffffffu, rs, 1);
                rs += __shfl_xor_sync(0xffffffffu, rs, 2);
                l_i[rr] = l_i[rr] * alpha + rs;
                #pragma unroll
                for (int j = 0; j < 8; j++) {
                    o[j][2 * rr    ] *= alpha;
                    o[j][2 * rr + 1] *= alpha;
                }
            }

            #pragma unroll
            for (int j = 0; j < 8; j++) {
                __half h0, l0, h1, l1, h2, l2, h3, l3;
                split_hf(s[j][0], h0, l0); split_hf(s[j][1], h1, l1);
                split_hf(s[j][2], h2, l2); split_hf(s[j][3], h3, l3);
                const int p0 = (rw + g) * QSTR + 8 * j + 2 * t;
                const int p1 = p0 + 8 * QSTR;
                *(unsigned*)&Ph[p0] = pk(h0, h1);
                *(unsigned*)&Pl[p0] = pk(l0, l1);
                *(unsigned*)&Ph[p1] = pk(h2, h3);
                *(unsigned*)&Pl[p1] = pk(l2, l3);
            }
            __syncwarp();

            // ---- O += P @ V ----
            #pragma unroll
            for (int ks = 0; ks < 4; ks++) {
                const int kk = 16 * ks;
                unsigned ph[4], plr[4];
                ldsm4(ph,  Ph + rw * QSTR + kk + aoffQ);
                ldsm4(plr, Pl + rw * QSTR + kk + aoffQ);
                #pragma unroll
                for (int p = 0; p < 2; p++) {
                    unsigned bh0[4], bl0[4], bh1[4], bl1[4];
                    ldsm4(bh0, Vh + (32 * p     ) * QSTR + kk + boffQ);
                    ldsm4(bl0, Vl + (32 * p     ) * QSTR + kk + boffQ);
                    ldsm4(bh1, Vh + (32 * p + 16) * QSTR + kk + boffQ);
                    ldsm4(bl1, Vl + (32 * p + 16) * QSTR + kk + boffQ);
                    const int j0 = 4 * p;
                    mmaF(o[j0 + 0], ph, bh0[0], bh0[1]);
                    mmaF(o[j0 + 1], ph, bh0[2], bh0[3]);
                    mmaF(o[j0 + 2], ph, bh1[0], bh1[1]);
                    mmaF(o[j0 + 3], ph, bh1[2], bh1[3]);
                    unsigned cc[4][2];
                    mmaH0(cc[0], plr, bh0[0], bh0[1]);
                    mmaH0(cc[1], plr, bh0[2], bh0[3]);
                    mmaH0(cc[2], plr, bh1[0], bh1[1]);
                    mmaH0(cc[3], plr, bh1[2], bh1[3]);
                    mmaH(cc[0], ph, bl0[0], bl0[1]);
                    mmaH(cc[1], ph, bl0[2], bl0[3]);
                    mmaH(cc[2], ph, bl1[0], bl1[1]);
                    mmaH(cc[3], ph, bl1[2], bl1[3]);
                    #pragma unroll
                    for (int jj = 0; jj < 4; jj++) foldcc(o[j0 + jj], cc[jj]);
                }
            }
        }
        __syncthreads();
    }

    const float inv0 = 1.f / l_i[0];
    const float inv1 = 1.f / l_i[1];
    const int row0 = qt * 128 + rw + g;
    const size_t d0 = ((size_t)b * SEQ + row0    ) * D_MODEL + h * D_HEAD;
    const size_t d1 = ((size_t)b * SEQ + row0 + 8) * D_MODEL + h * D_HEAD;
    #pragma unroll
    for (int j = 0; j < 8; j++) {
        const int cidx = 8 * j + 2 * t;
        __half h0, l0, h1, l1, h2, l2, h3, l3;
        split_hf(o[j][0] * inv0, h0, l0); split_hf(o[j][1] * inv0, h1, l1);
        split_hf(o[j][2] * inv1, h2, l2); split_hf(o[j][3] * inv1, h3, l3);
        *(unsigned*)&g_ch[d0 + cidx] = pk(h0, h1);
        *(unsigned*)&g_cl[d0 + cidx] = pk(l0, l1);
        *(unsigned*)&g_ch[d1 + cidx] = pk(h2, h3);
        *(unsigned*)&g_cl[d1 + cidx] = pk(l2, l3);
    }
}

// ---------------- launch ----------------------------------------------------
extern "C" void kernel_launch(void* const* d_in, const int* in_sizes, int n_in,
                              void* d_out, int out_size)
{
    (void)in_sizes; (void)n_in; (void)out_size;
    const float* x  = (const float*)d_in[0];
    const float* Qw = (const float*)d_in[1];
    const float* Kw = (const float*)d_in[2];
    const float* Vw = (const float*)d_in[3];
    const float* Ow = (const float*)d_in[4];
    const unsigned char* pm = (const unsigned char*)d_in[5];
    float* out = (float*)d_out;

    cudaFuncSetAttribute(attn_mma, cudaFuncAttributeMaxDynamicSharedMemorySize, ATTN_SMEM);
    cudaFuncSetAttribute(gemm_qkv, cudaFuncAttributeMaxDynamicSharedMemorySize, GEMM_SMEM);
    cudaFuncSetAttribute(gemm_out, cudaFuncAttributeMaxDynamicSharedMemorySize, GEMM_SMEM);

    split_all<<<12288, 256>>>(x, Qw, Kw, Vw, Ow);

    dim3 gq(D_MODEL / 128, MTOT / 128, 3);        // 8 x 64 x 3
    gemm_qkv<<<gq, 256, GEMM_SMEM>>>();

    dim3 ga(SEQ / 128, NUM_HEADS, BATCH);         // 16 x 16 x 4
    attn_mma<<<ga, 256, ATTN_SMEM>>>(pm);

    dim3 go(D_MODEL / 128, MTOT / 128);           // 8 x 64
    gemm_out<<<go, 256, GEMM_SMEM>>>(out);
}

// round 10
// speedup vs baseline: 1.6793x; 1.6793x over previous
#include <cuda_runtime.h>
#include <cuda_fp16.h>
#include <cstdint>

#define D_MODEL   1024
#define NUM_HEADS 16
#define D_HEAD    64
#define BATCH     4
#define SEQ       2048
#define MTOT      (BATCH * SEQ)   // 8192
#define QKV_EL    (BATCH * NUM_HEADS * SEQ * D_HEAD)   // 8388608

// ---------------- scratch (device globals: allocation-guard safe) ----------
__device__ __half g_xh[MTOT * D_MODEL],  g_xl[MTOT * D_MODEL];
__device__ __half g_wh[4][D_MODEL * D_MODEL];          // weights: single fp16
__device__ __half g_qh[QKV_EL], g_ql[QKV_EL];          // [b,h,s,d] split
__device__ __half g_kh[QKV_EL];                        // [b,h,s,d] single
__device__ __half g_vth[QKV_EL];                       // [b,h,d,s] single
__device__ __half g_ch[MTOT * D_MODEL], g_cl[MTOT * D_MODEL];   // ctx split

// ---------------- helpers ----------------------------------------------------
__device__ __forceinline__ void split_hf(float x, __half& h, __half& l) {
    h = __float2half_rn(x);
    l = __float2half_rn(x - __half2float(h));
}
__device__ __forceinline__ unsigned pk(__half a, __half b) {
    return (unsigned)__half_as_ushort(a) | ((unsigned)__half_as_ushort(b) << 16);
}
__device__ __forceinline__ void split_store4(float4 v, __half* hp, __half* lp) {
    __half h0, l0, h1, l1, h2, l2, h3, l3;
    split_hf(v.x, h0, l0); split_hf(v.y, h1, l1);
    split_hf(v.z, h2, l2); split_hf(v.w, h3, l3);
    *(uint2*)hp = make_uint2(pk(h0, h1), pk(h2, h3));
    *(uint2*)lp = make_uint2(pk(l0, l1), pk(l2, l3));
}
__device__ __forceinline__ void round_store4(float4 v, __half* hp) {
    *(uint2*)hp = make_uint2(pk(__float2half_rn(v.x), __float2half_rn(v.y)),
                             pk(__float2half_rn(v.z), __float2half_rn(v.w)));
}
// fp32-accumulator mma (fp16 inputs)
__device__ __forceinline__ void mmaF(float* c, const unsigned* a, unsigned b0, unsigned b1) {
    asm volatile(
        "mma.sync.aligned.m16n8k16.row.col.f32.f16.f16.f32 "
        "{%0,%1,%2,%3}, {%4,%5,%6,%7}, {%8,%9}, {%0,%1,%2,%3};"
        : "+f"(c[0]), "+f"(c[1]), "+f"(c[2]), "+f"(c[3])
        : "r"(a[0]), "r"(a[1]), "r"(a[2]), "r"(a[3]), "r"(b0), "r"(b1));
}
__device__ __forceinline__ void ldsm4(unsigned r[4], const __half* p) {
    unsigned a = (unsigned)__cvta_generic_to_shared(p);
    asm volatile("ldmatrix.sync.aligned.m8n8.x4.shared.b16 {%0,%1,%2,%3}, [%4];"
                 : "=r"(r[0]), "=r"(r[1]), "=r"(r[2]), "=r"(r[3]) : "r"(a));
}
__device__ __forceinline__ void cp16(__half* s, const __half* g) {
    unsigned sa = (unsigned)__cvta_generic_to_shared(s);
    asm volatile("cp.async.cg.shared.global [%0], [%1], 16;" :: "r"(sa), "l"(g));
}
#define CP_COMMIT() asm volatile("cp.async.commit_group;")
#define CP_WAIT0()  asm volatile("cp.async.wait_group 0;")
#define CP_WAIT1()  asm volatile("cp.async.wait_group 1;")

// fast exp2 on the FMA pipe (MUFU-free)
__device__ __forceinline__ float exp2_fast(float y) {
    y = fmaxf(y, -120.f);
    float z = y + 12582912.f;
    int   e = __float_as_int(z);
    float f = y - (z - 12582912.f);
    float p = 1.f + f * (0.6931471805599453f + f * (0.2402265069591007f +
              f * (0.0555041086648216f + f * (0.0096181291076285f +
              f * 0.0013333558146429f))));
    return __int_as_float(__float_as_int(p) + (e << 23));
}
#define SCALE_LOG2E 0.18033688011112042f   // 0.125 * log2(e)

// ---------------- one-shot split of x + round of weights ---------------------
// 2M float4 for x (split), 1M float4 for 4 weights (round). 3,145,728 total.
__global__ __launch_bounds__(256) void split_all(const float* __restrict__ x,
                                                 const float* __restrict__ Qw,
                                                 const float* __restrict__ Kw,
                                                 const float* __restrict__ Vw,
                                                 const float* __restrict__ Ow)
{
    const int idx = blockIdx.x * 256 + threadIdx.x;        // one float4 each
    if (idx < 2097152) {
        float4 v = ((const float4*)x)[idx];
        split_store4(v, g_xh + (size_t)idx * 4, g_xl + (size_t)idx * 4);
    } else {
        const int w = (idx - 2097152) >> 18;
        const size_t off = (size_t)((idx - 2097152) & 262143);
        const float* src = (w == 0) ? Qw : (w == 1) ? Kw : (w == 2) ? Vw : Ow;
        float4 v = ((const float4*)src)[off];
        round_store4(v, g_wh[w] + off * 4);
    }
}

// ---------------- 2-term fp16 GEMM: C = (Ahi + Alo) @ Wh^T -------------------
// Block tile 128x128, BK=32, 256 threads = 8 warps (4m x 2n), warp tile 32x64.
#define SSTR 40
#define GBUF (128 * SSTR)
#define GSTG (3 * GBUF)               // Ah, Al, Bh
#define GEMM_SMEM (2 * GSTG * 2)      // 61440 bytes

__device__ __forceinline__ void gemm_hf_body(const __half* __restrict__ Agh,
                                             const __half* __restrict__ Agl,
                                             const __half* __restrict__ Bgh,
                                             int m0, int n0,
                                             float (&c)[2][8][4],
                                             __half* sm)
{
    const int tid  = threadIdx.x;
    const int lane = tid & 31;
    const int warp = tid >> 5;
    const int wm   = (warp >> 1) * 32;
    const int wn   = (warp & 1) * 64;
    const int lrow = tid >> 1;
    const int lcol = (tid & 1) * 16;
    const int so   = lrow * SSTR + lcol;

    const int aoff = ((lane & 7) + ((lane >> 3) & 1) * 8) * SSTR + (lane >> 4) * 8;
    const int boff = ((lane & 7) + (lane >> 4) * 8) * SSTR + ((lane >> 3) & 1) * 8;

    const size_t arow = (size_t)(m0 + lrow) * D_MODEL + lcol;
    const size_t brow = (size_t)(n0 + lrow) * D_MODEL + lcol;

    {   // prologue: stage 0 <- k-tile 0
        __half* st = sm;
        cp16(st + so,            Agh + arow); cp16(st + so + 8,            Agh + arow + 8);
        cp16(st + GBUF + so,     Agl + arow); cp16(st + GBUF + so + 8,     Agl + arow + 8);
        cp16(st + 2 * GBUF + so, Bgh + brow); cp16(st + 2 * GBUF + so + 8, Bgh + brow + 8);
        CP_COMMIT();
        CP_WAIT0();
    }
    __syncthreads();

    for (int kt = 0; kt < 32; kt++) {
        if (kt + 1 < 32) {
            __half* nx = sm + ((kt + 1) & 1) * GSTG;
            const int k0 = (kt + 1) * 32;
            cp16(nx + so,            Agh + arow + k0); cp16(nx + so + 8,            Agh + arow + k0 + 8);
            cp16(nx + GBUF + so,     Agl + arow + k0); cp16(nx + GBUF + so + 8,     Agl + arow + k0 + 8);
            cp16(nx + 2 * GBUF + so, Bgh + brow + k0); cp16(nx + 2 * GBUF + so + 8, Bgh + brow + k0 + 8);
            CP_COMMIT();
        }

        const __half* Ah = sm + (kt & 1) * GSTG;
        const __half* Al = Ah + GBUF;
        const __half* Bh = Ah + 2 * GBUF;

        #pragma unroll
        for (int ks = 0; ks < 2; ks++) {
            const int kk = ks * 16;
            unsigned ahi[2][4], alo[2][4];
            ldsm4(ahi[0], Ah + (wm     ) * SSTR + kk + aoff);
            ldsm4(ahi[1], Ah + (wm + 16) * SSTR + kk + aoff);
            ldsm4(alo[0], Al + (wm     ) * SSTR + kk + aoff);
            ldsm4(alo[1], Al + (wm + 16) * SSTR + kk + aoff);
            #pragma unroll
            for (int p = 0; p < 2; p++) {
                unsigned bh0[4], bh1[4];
                ldsm4(bh0, Bh + (wn + 32 * p     ) * SSTR + kk + boff);
                ldsm4(bh1, Bh + (wn + 32 * p + 16) * SSTR + kk + boff);
                const int j0 = 4 * p;
                // hi term (8 independent accumulators)
                mmaF(c[0][j0 + 0], ahi[0], bh0[0], bh0[1]);
                mmaF(c[1][j0 + 0], ahi[1], bh0[0], bh0[1]);
                mmaF(c[0][j0 + 1], ahi[0], bh0[2], bh0[3]);
                mmaF(c[1][j0 + 1], ahi[1], bh0[2], bh0[3]);
                mmaF(c[0][j0 + 2], ahi[0], bh1[0], bh1[1]);
                mmaF(c[1][j0 + 2], ahi[1], bh1[0], bh1[1]);
                mmaF(c[0][j0 + 3], ahi[0], bh1[2], bh1[3]);
                mmaF(c[1][j0 + 3], ahi[1], bh1[2], bh1[3]);
                // lo term
                mmaF(c[0][j0 + 0], alo[0], bh0[0], bh0[1]);
                mmaF(c[1][j0 + 0], alo[1], bh0[0], bh0[1]);
                mmaF(c[0][j0 + 1], alo[0], bh0[2], bh0[3]);
                mmaF(c[1][j0 + 1], alo[1], bh0[2], bh0[3]);
                mmaF(c[0][j0 + 2], alo[0], bh1[0], bh1[1]);
                mmaF(c[1][j0 + 2], alo[1], bh1[0], bh1[1]);
                mmaF(c[0][j0 + 3], alo[0], bh1[2], bh1[3]);
                mmaF(c[1][j0 + 3], alo[1], bh1[2], bh1[3]);
            }
        }
        CP_WAIT0();
        __syncthreads();
    }
}

// Fused QKV projection; blockIdx.z selects weight.
// Q -> split [b,h,s,d]; K -> single [b,h,s,d]; V -> single transposed [b,h,d,s].
__global__ __launch_bounds__(256, 2) void gemm_qkv()
{
    extern __shared__ __half smg[];
    float c[2][8][4];
    #pragma unroll
    for (int i = 0; i < 2; i++)
        #pragma unroll
        for (int j = 0; j < 8; j++)
            #pragma unroll
            for (int q = 0; q < 4; q++) c[i][j][q] = 0.f;

    const int m0 = blockIdx.y * 128;
    const int n0 = blockIdx.x * 128;
    const int z  = blockIdx.z;

    gemm_hf_body(g_xh, g_xl, g_wh[z], m0, n0, c, smg);

    const int lane = threadIdx.x & 31;
    const int g = lane >> 2, t = lane & 3;
    const int warp = threadIdx.x >> 5;
    const int wm = (warp >> 1) * 32, wn = (warp & 1) * 64;

    #pragma unroll
    for (int i = 0; i < 2; i++) {
        #pragma unroll
        for (int j = 0; j < 8; j++) {
            const int n = n0 + wn + 8 * j + 2 * t;
            const int h = n >> 6, d = n & 63;
            const int r0 = m0 + wm + 16 * i + g;
            const int r1 = r0 + 8;
            const int b0 = r0 >> 11, s0 = r0 & 2047;
            const int b1 = r1 >> 11, s1 = r1 & 2047;
            if (z == 0) {
                __half h0, l0, h1, l1, h2, l2, h3, l3;
                split_hf(c[i][j][0], h0, l0); split_hf(c[i][j][1], h1, l1);
                split_hf(c[i][j][2], h2, l2); split_hf(c[i][j][3], h3, l3);
                const size_t i0 = ((size_t)(b0 * NUM_HEADS + h) * SEQ + s0) * D_HEAD + d;
                const size_t i1 = ((size_t)(b1 * NUM_HEADS + h) * SEQ + s1) * D_HEAD + d;
                *(unsigned*)&g_qh[i0] = pk(h0, h1);
                *(unsigned*)&g_ql[i0] = pk(l0, l1);
                *(unsigned*)&g_qh[i1] = pk(h2, h3);
                *(unsigned*)&g_ql[i1] = pk(l2, l3);
            } else if (z == 1) {
                const size_t i0 = ((size_t)(b0 * NUM_HEADS + h) * SEQ + s0) * D_HEAD + d;
                const size_t i1 = ((size_t)(b1 * NUM_HEADS + h) * SEQ + s1) * D_HEAD + d;
                *(unsigned*)&g_kh[i0] = pk(__float2half_rn(c[i][j][0]),
                                           __float2half_rn(c[i][j][1]));
                *(unsigned*)&g_kh[i1] = pk(__float2half_rn(c[i][j][2]),
                                           __float2half_rn(c[i][j][3]));
            } else {
                const size_t v0 = ((size_t)(b0 * NUM_HEADS + h) * D_HEAD + d) * SEQ + s0;
                const size_t v1 = ((size_t)(b1 * NUM_HEADS + h) * D_HEAD + d) * SEQ + s1;
                g_vth[v0]       = __float2half_rn(c[i][j][0]);
                g_vth[v0 + SEQ] = __float2half_rn(c[i][j][1]);   // d+1
                g_vth[v1]       = __float2half_rn(c[i][j][2]);
                g_vth[v1 + SEQ] = __float2half_rn(c[i][j][3]);
            }
        }
    }
}

// Output projection: out = ctx @ Ow^T, fp32 out.
__global__ __launch_bounds__(256, 2) void gemm_out(float* __restrict__ out)
{
    extern __shared__ __half smg[];
    float c[2][8][4];
    #pragma unroll
    for (int i = 0; i < 2; i++)
        #pragma unroll
        for (int j = 0; j < 8; j++)
            #pragma unroll
            for (int q = 0; q < 4; q++) c[i][j][q] = 0.f;

    const int m0 = blockIdx.y * 128;
    const int n0 = blockIdx.x * 128;

    gemm_hf_body(g_ch, g_cl, g_wh[3], m0, n0, c, smg);

    const int lane = threadIdx.x & 31;
    const int g = lane >> 2, t = lane & 3;
    const int warp = threadIdx.x >> 5;
    const int wm = (warp >> 1) * 32, wn = (warp & 1) * 64;

    #pragma unroll
    for (int i = 0; i < 2; i++) {
        #pragma unroll
        for (int j = 0; j < 8; j++) {
            const int n  = n0 + wn + 8 * j + 2 * t;
            const int r0 = m0 + wm + 16 * i + g;
            *(float2*)&out[(size_t)r0 * D_MODEL + n] = make_float2(c[i][j][0], c[i][j][1]);
            *(float2*)&out[(size_t)(r0 + 8) * D_MODEL + n] = make_float2(c[i][j][2], c[i][j][3]);
        }
    }
}

// ---------------- Flash attention: 2-term (Q,P split; K,V single) ------------
// Block = (b, h, 128-q-tile). 256 threads = 8 warps. KV tiles of 64.
// KV stage = {Kh, Vth} = 2 tiles; Q staged over both stages, then reg-resident.
#define QSTR 72
#define TILEC (64 * QSTR)
#define ATTN_SMEM (8 * TILEC * 2)         // 73728 bytes

__global__ __launch_bounds__(256, 2) void attn_mma(const unsigned char* __restrict__ pm)
{
    extern __shared__ __half smb[];
    __half* stg0 = smb;                   // {Kh, Vth} stage 0
    __half* stg1 = smb + 2 * TILEC;       // stage 1
    __half* Ph   = smb + 4 * TILEC;       // P hi (128 rows = 2 TILEC)
    __half* Pl   = smb + 6 * TILEC;       // P lo

    const int qt = gridDim.x - 1 - blockIdx.x;
    const int h  = blockIdx.y;
    const int b  = blockIdx.z;
    const int tid  = threadIdx.x;
    const int lane = tid & 31;
    const int warp = tid >> 5;
    const int g = lane >> 2, t = lane & 3;
    const size_t base = (size_t)(b * NUM_HEADS + h) * SEQ;

    const int rw = warp * 16;
    const int Rg = qt * 128 + rw;
    const int kt_max = 2 * qt + 1;

    const int aoffQ = ((lane & 7) + ((lane >> 3) & 1) * 8) * QSTR + (lane >> 4) * 8;
    const int boffQ = ((lane & 7) + (lane >> 4) * 8) * QSTR + ((lane >> 3) & 1) * 8;

    const int krow = tid >> 2;
    const int kcs  = (tid & 3) * 16;
    const int kso  = krow * QSTR + kcs;
    const size_t vbase = ((size_t)(b * NUM_HEADS + h) * D_HEAD + krow) * SEQ + kcs;
    const size_t kbase = (base + krow) * D_HEAD + kcs;

    // ---- stage Q (hi into smb[0..2T), lo into smb[2T..4T)), move to regs ----
    {
        const int row = tid >> 1, cs = (tid & 1) * 32;
        const size_t ga = (base + (size_t)qt * 128 + row) * D_HEAD + cs;
        const int so = row * QSTR + cs;
        #pragma unroll
        for (int u = 0; u < 4; u++) {
            cp16(&smb[so + 8 * u],             &g_qh[ga + 8 * u]);
            cp16(&smb[2 * TILEC + so + 8 * u], &g_ql[ga + 8 * u]);
        }
        CP_COMMIT();
        CP_WAIT0();
    }
    __syncthreads();

    unsigned qh[4][4], ql[4][4];
    #pragma unroll
    for (int ks = 0; ks < 4; ks++) {
        ldsm4(qh[ks], smb + rw * QSTR + 16 * ks + aoffQ);
        ldsm4(ql[ks], smb + 2 * TILEC + rw * QSTR + 16 * ks + aoffQ);
    }
    __syncthreads();                      // smem free for KV stages

    // ---- prologue: KV(0) into stg0 ----
    {
        cp16(&stg0[kso],         &g_kh[kbase]);  cp16(&stg0[kso + 8],         &g_kh[kbase + 8]);
        cp16(&stg0[TILEC + kso], &g_vth[vbase]); cp16(&stg0[TILEC + kso + 8], &g_vth[vbase + 8]);
        CP_COMMIT();
    }

    float o[8][4];
    float m_i[2] = {-1e30f, -1e30f};
    float l_i[2] = {0.f, 0.f};
    #pragma unroll
    for (int j = 0; j < 8; j++)
        #pragma unroll
        for (int q = 0; q < 4; q++) o[j][q] = 0.f;

    for (int kt = 0; kt <= kt_max; kt++) {
        if (kt < kt_max) {
            __half* nx = ((kt + 1) & 1) ? stg1 : stg0;
            const size_t gk = kbase + (size_t)(kt + 1) * 64 * D_HEAD;
            const size_t gv = vbase + (size_t)(kt + 1) * 64;
            cp16(&nx[kso],         &g_kh[gk]);  cp16(&nx[kso + 8],         &g_kh[gk + 8]);
            cp16(&nx[TILEC + kso], &g_vth[gv]); cp16(&nx[TILEC + kso + 8], &g_vth[gv + 8]);
            CP_COMMIT();
            CP_WAIT1();                    // KV(kt) complete
        } else {
            CP_WAIT0();
        }
        __syncthreads();

        const int C0 = kt * 64;
        if (C0 <= Rg + 15) {
            const __half* Kh = (kt & 1) ? stg1 : stg0;
            const __half* Vh = Kh + TILEC;

            float s[8][4];
            #pragma unroll
            for (int j = 0; j < 8; j++)
                #pragma unroll
                for (int q = 0; q < 4; q++) s[j][q] = 0.f;

            // ---- S = (Qhi + Qlo) @ Kh^T ----
            #pragma unroll
            for (int ks = 0; ks < 4; ks++) {
                const int kk = 16 * ks;
                #pragma unroll
                for (int p = 0; p < 2; p++) {
                    unsigned bh0[4], bh1[4];
                    ldsm4(bh0, Kh + (32 * p     ) * QSTR + kk + boffQ);
                    ldsm4(bh1, Kh + (32 * p + 16) * QSTR + kk + boffQ);
                    const int j0 = 4 * p;
                    mmaF(s[j0 + 0], qh[ks], bh0[0], bh0[1]);
                    mmaF(s[j0 + 1], qh[ks], bh0[2], bh0[3]);
                    mmaF(s[j0 + 2], qh[ks], bh1[0], bh1[1]);
                    mmaF(s[j0 + 3], qh[ks], bh1[2], bh1[3]);
                    mmaF(s[j0 + 0], ql[ks], bh0[0], bh0[1]);
                    mmaF(s[j0 + 1], ql[ks], bh0[2], bh0[3]);
                    mmaF(s[j0 + 2], ql[ks], bh1[0], bh1[1]);
                    mmaF(s[j0 + 3], ql[ks], bh1[2], bh1[3]);
                }
            }

            // ---- scale (log2 domain) + causal + padding masks ----
            const unsigned char* pmb = pm + (size_t)b * SEQ + C0;
            const int r0 = Rg + g, r1 = r0 + 8;
            #pragma unroll
            for (int j = 0; j < 8; j++) {
                const int c0 = C0 + 8 * j + 2 * t, c1 = c0 + 1;
                const bool p0 = pmb[8 * j + 2 * t] != 0;
                const bool p1 = pmb[8 * j + 2 * t + 1] != 0;
                float v;
                v = s[j][0] * SCALE_LOG2E; if (c0 > r0 || p0) v = -1e30f; s[j][0] = v;
                v = s[j][1] * SCALE_LOG2E; if (c1 > r0 || p1) v = -1e30f; s[j][1] = v;
                v = s[j][2] * SCALE_LOG2E; if (c0 > r1 || p0) v = -1e30f; s[j][2] = v;
                v = s[j][3] * SCALE_LOG2E; if (c1 > r1 || p1) v = -1e30f; s[j][3] = v;
            }

            // ---- online softmax, base-2, FMA-pipe exp ----
            #pragma unroll
            for (int rr = 0; rr < 2; rr++) {
                float rm = -1e30f;
                #pragma unroll
                for (int j = 0; j < 8; j++)
                    rm = fmaxf(rm, fmaxf(s[j][2 * rr], s[j][2 * rr + 1]));
                rm = fmaxf(rm, __shfl_xor_sync(0xffffffffu, rm, 1));
                rm = fmaxf(rm, __shfl_xor_sync(0xffffffffu, rm, 2));
                const float mn    = fmaxf(m_i[rr], rm);
                const float alpha = exp2_fast(m_i[rr] - mn);
                m_i[rr] = mn;
                float rs = 0.f;
                #pragma unroll
                for (int j = 0; j < 8; j++) {
                    s[j][2 * rr    ] = exp2_fast(s[j][2 * rr    ] - mn);
                    s[j][2 * rr + 1] = exp2_fast(s[j][2 * rr + 1] - mn);
                    rs += s[j][2 * rr] + s[j][2 * rr + 1];
                }
                rs += __shfl_xor_sync(0xffffffffu, rs, 1);
                rs += __shfl_xor_sync(0xffffffffu, rs, 2);
                l_i[rr] = l_i[rr] * alpha + rs;
                #pragma unroll
                for (int j = 0; j < 8; j++) {
                    o[j][2 * rr    ] *= alpha;
                    o[j][2 * rr + 1] *= alpha;
                }
            }

            // ---- split-write P (warp-private rows) ----
            #pragma unroll
            for (int j = 0; j < 8; j++) {
                __half h0, l0, h1, l1, h2, l2, h3, l3;
                split_hf(s[j][0], h0, l0); split_hf(s[j][1], h1, l1);
                split_hf(s[j][2], h2, l2); split_hf(s[j][3], h3, l3);
                const int p0 = (rw + g) * QSTR + 8 * j + 2 * t;
                const int p1 = p0 + 8 * QSTR;
                *(unsigned*)&Ph[p0] = pk(h0, h1);
                *(unsigned*)&Pl[p0] = pk(l0, l1);
                *(unsigned*)&Ph[p1] = pk(h2, h3);
                *(unsigned*)&Pl[p1] = pk(l2, l3);
            }
            __syncwarp();

            // ---- O += (Phi + Plo) @ Vh ----
            #pragma unroll
            for (int ks = 0; ks < 4; ks++) {
                const int kk = 16 * ks;
                unsigned ph[4], plr[4];
                ldsm4(ph,  Ph + rw * QSTR + kk + aoffQ);
                ldsm4(plr, Pl + rw * QSTR + kk + aoffQ);
                #pragma unroll
                for (int p = 0; p < 2; p++) {
                    unsigned bh0[4], bh1[4];
                    ldsm4(bh0, Vh + (32 * p     ) * QSTR + kk + boffQ);
                    ldsm4(bh1, Vh + (32 * p + 16) * QSTR + kk + boffQ);
                    const int j0 = 4 * p;
                    mmaF(o[j0 + 0], ph, bh0[0], bh0[1]);
                    mmaF(o[j0 + 1], ph, bh0[2], bh0[3]);
                    mmaF(o[j0 + 2], ph, bh1[0], bh1[1]);
                    mmaF(o[j0 + 3], ph, bh1[2], bh1[3]);
                    mmaF(o[j0 + 0], plr, bh0[0], bh0[1]);
                    mmaF(o[j0 + 1], plr, bh0[2], bh0[3]);
                    mmaF(o[j0 + 2], plr, bh1[0], bh1[1]);
                    mmaF(o[j0 + 3], plr, bh1[2], bh1[3]);
                }
            }
        }
        __syncthreads();
    }

    // ---- normalize + split-write ctx ----
    const float inv0 = 1.f / l_i[0];
    const float inv1 = 1.f / l_i[1];
    const int row0 = qt * 128 + rw + g;
    const size_t d0 = ((size_t)b * SEQ + row0    ) * D_MODEL + h * D_HEAD;
    const size_t d1 = ((size_t)b * SEQ + row0 + 8) * D_MODEL + h * D_HEAD;
    #pragma unroll
    for (int j = 0; j < 8; j++) {
        const int cidx = 8 * j + 2 * t;
        __half h0, l0, h1, l1, h2, l2, h3, l3;
        split_hf(o[j][0] * inv0, h0, l0); split_hf(o[j][1] * inv0, h1, l1);
        split_hf(o[j][2] * inv1, h2, l2); split_hf(o[j][3] * inv1, h3, l3);
        *(unsigned*)&g_ch[d0 + cidx] = pk(h0, h1);
        *(unsigned*)&g_cl[d0 + cidx] = pk(l0, l1);
        *(unsigned*)&g_ch[d1 + cidx] = pk(h2, h3);
        *(unsigned*)&g_cl[d1 + cidx] = pk(l2, l3);
    }
}

// ---------------- launch ----------------------------------------------------
extern "C" void kernel_launch(void* const* d_in, const int* in_sizes, int n_in,
                              void* d_out, int out_size)
{
    (void)in_sizes; (void)n_in; (void)out_size;
    const float* x  = (const float*)d_in[0];
    const float* Qw = (const float*)d_in[1];
    const float* Kw = (const float*)d_in[2];
    const float* Vw = (const float*)d_in[3];
    const float* Ow = (const float*)d_in[4];
    const unsigned char* pm = (const unsigned char*)d_in[5];
    float* out = (float*)d_out;

    cudaFuncSetAttribute(attn_mma, cudaFuncAttributeMaxDynamicSharedMemorySize, ATTN_SMEM);
    cudaFuncSetAttribute(gemm_qkv, cudaFuncAttributeMaxDynamicSharedMemorySize, GEMM_SMEM);
    cudaFuncSetAttribute(gemm_out, cudaFuncAttributeMaxDynamicSharedMemorySize, GEMM_SMEM);

    split_all<<<12288, 256>>>(x, Qw, Kw, Vw, Ow);

    dim3 gq(D_MODEL / 128, MTOT / 128, 3);        // 8 x 64 x 3
    gemm_qkv<<<gq, 256, GEMM_SMEM>>>();

    dim3 ga(SEQ / 128, NUM_HEADS, BATCH);         // 16 x 16 x 4
    attn_mma<<<ga, 256, ATTN_SMEM>>>(pm);

    dim3 go(D_MODEL / 128, MTOT / 128);           // 8 x 64
    gemm_out<<<go, 256, GEMM_SMEM>>>(out);
}

// round 11
// speedup vs baseline: 1.9200x; 1.1433x over previous
#include <cuda_runtime.h>
#include <cuda_fp16.h>
#include <cstdint>

#define D_MODEL   1024
#define NUM_HEADS 16
#define D_HEAD    64
#define BATCH     4
#define SEQ       2048
#define MTOT      (BATCH * SEQ)   // 8192
#define QKV_EL    (BATCH * NUM_HEADS * SEQ * D_HEAD)   // 8388608

// ---------------- scratch (device globals: allocation-guard safe) ----------
__device__ __half g_xh[MTOT * D_MODEL],  g_xl[MTOT * D_MODEL];
__device__ __half g_wh[4][D_MODEL * D_MODEL];          // weights: single fp16
__device__ __half g_qh[QKV_EL], g_ql[QKV_EL];          // [b,h,s,d] split
__device__ __half g_kh[QKV_EL];                        // [b,h,s,d] single
__device__ __half g_vth[QKV_EL];                       // [b,h,d,s] single
__device__ __half g_ch[MTOT * D_MODEL];                // ctx single

// ---------------- helpers ----------------------------------------------------
__device__ __forceinline__ void split_hf(float x, __half& h, __half& l) {
    h = __float2half_rn(x);
    l = __float2half_rn(x - __half2float(h));
}
__device__ __forceinline__ unsigned pk(__half a, __half b) {
    return (unsigned)__half_as_ushort(a) | ((unsigned)__half_as_ushort(b) << 16);
}
__device__ __forceinline__ void split_store4(float4 v, __half* hp, __half* lp) {
    __half h0, l0, h1, l1, h2, l2, h3, l3;
    split_hf(v.x, h0, l0); split_hf(v.y, h1, l1);
    split_hf(v.z, h2, l2); split_hf(v.w, h3, l3);
    *(uint2*)hp = make_uint2(pk(h0, h1), pk(h2, h3));
    *(uint2*)lp = make_uint2(pk(l0, l1), pk(l2, l3));
}
__device__ __forceinline__ void round_store4(float4 v, __half* hp) {
    *(uint2*)hp = make_uint2(pk(__float2half_rn(v.x), __float2half_rn(v.y)),
                             pk(__float2half_rn(v.z), __float2half_rn(v.w)));
}
// fp32-accumulator mma (fp16 inputs)
__device__ __forceinline__ void mmaF(float* c, const unsigned* a, unsigned b0, unsigned b1) {
    asm volatile(
        "mma.sync.aligned.m16n8k16.row.col.f32.f16.f16.f32 "
        "{%0,%1,%2,%3}, {%4,%5,%6,%7}, {%8,%9}, {%0,%1,%2,%3};"
        : "+f"(c[0]), "+f"(c[1]), "+f"(c[2]), "+f"(c[3])
        : "r"(a[0]), "r"(a[1]), "r"(a[2]), "r"(a[3]), "r"(b0), "r"(b1));
}
__device__ __forceinline__ void ldsm4(unsigned r[4], const __half* p) {
    unsigned a = (unsigned)__cvta_generic_to_shared(p);
    asm volatile("ldmatrix.sync.aligned.m8n8.x4.shared.b16 {%0,%1,%2,%3}, [%4];"
                 : "=r"(r[0]), "=r"(r[1]), "=r"(r[2]), "=r"(r[3]) : "r"(a));
}
__device__ __forceinline__ void cp16(__half* s, const __half* g) {
    unsigned sa = (unsigned)__cvta_generic_to_shared(s);
    asm volatile("cp.async.cg.shared.global [%0], [%1], 16;" :: "r"(sa), "l"(g));
}
#define CP_COMMIT() asm volatile("cp.async.commit_group;")
#define CP_WAIT0()  asm volatile("cp.async.wait_group 0;")
#define CP_WAIT1()  asm volatile("cp.async.wait_group 1;")

// fast exp2 on the FMA pipe (MUFU-free)
__device__ __forceinline__ float exp2_fast(float y) {
    y = fmaxf(y, -120.f);
    float z = y + 12582912.f;
    int   e = __float_as_int(z);
    float f = y - (z - 12582912.f);
    float p = 1.f + f * (0.6931471805599453f + f * (0.2402265069591007f +
              f * (0.0555041086648216f + f * (0.0096181291076285f +
              f * 0.0013333558146429f))));
    return __int_as_float(__float_as_int(p) + (e << 23));
}
#define SCALE_LOG2E 0.18033688011112042f   // 0.125 * log2(e)

// ---------------- one-shot split of x + round of weights ---------------------
__global__ __launch_bounds__(256) void split_all(const float* __restrict__ x,
                                                 const float* __restrict__ Qw,
                                                 const float* __restrict__ Kw,
                                                 const float* __restrict__ Vw,
                                                 const float* __restrict__ Ow)
{
    const int idx = blockIdx.x * 256 + threadIdx.x;        // one float4 each
    if (idx < 2097152) {
        float4 v = ((const float4*)x)[idx];
        split_store4(v, g_xh + (size_t)idx * 4, g_xl + (size_t)idx * 4);
    } else {
        const int w = (idx - 2097152) >> 18;
        const size_t off = (size_t)((idx - 2097152) & 262143);
        const float* src = (w == 0) ? Qw : (w == 1) ? Kw : (w == 2) ? Vw : Ow;
        float4 v = ((const float4*)src)[off];
        round_store4(v, g_wh[w] + off * 4);
    }
}

// ---------------- fp16 GEMM body, templated on A-split -----------------------
// Block tile 128x128, BK=32, 256 threads = 8 warps (4m x 2n), warp tile 32x64.
#define SSTR 40
#define GBUF (128 * SSTR)
#define GEMM_SMEM_SPLIT  (2 * 3 * GBUF * 2)   // 61440 bytes (Ah, Al, Bh) x2
#define GEMM_SMEM_SINGLE (2 * 2 * GBUF * 2)   // 40960 bytes (Ah, Bh) x2

template<bool SPLIT>
__device__ __forceinline__ void gemm_hf_body(const __half* __restrict__ Agh,
                                             const __half* __restrict__ Agl,
                                             const __half* __restrict__ Bgh,
                                             int m0, int n0,
                                             float (&c)[2][8][4],
                                             __half* sm)
{
    constexpr int NT   = SPLIT ? 3 : 2;
    constexpr int GSTG = NT * GBUF;
    constexpr int BOFFB = (NT - 1) * GBUF;     // Bh tile offset within stage

    const int tid  = threadIdx.x;
    const int lane = tid & 31;
    const int warp = tid >> 5;
    const int wm   = (warp >> 1) * 32;
    const int wn   = (warp & 1) * 64;
    const int lrow = tid >> 1;
    const int lcol = (tid & 1) * 16;
    const int so   = lrow * SSTR + lcol;

    const int aoff = ((lane & 7) + ((lane >> 3) & 1) * 8) * SSTR + (lane >> 4) * 8;
    const int boff = ((lane & 7) + (lane >> 4) * 8) * SSTR + ((lane >> 3) & 1) * 8;

    const size_t arow = (size_t)(m0 + lrow) * D_MODEL + lcol;
    const size_t brow = (size_t)(n0 + lrow) * D_MODEL + lcol;

    {   // prologue: stage 0 <- k-tile 0
        __half* st = sm;
        cp16(st + so,         Agh + arow); cp16(st + so + 8,         Agh + arow + 8);
        if (SPLIT) {
            cp16(st + GBUF + so,     Agl + arow);
            cp16(st + GBUF + so + 8, Agl + arow + 8);
        }
        cp16(st + BOFFB + so, Bgh + brow); cp16(st + BOFFB + so + 8, Bgh + brow + 8);
        CP_COMMIT();
        CP_WAIT0();
    }
    __syncthreads();

    for (int kt = 0; kt < 32; kt++) {
        if (kt + 1 < 32) {
            __half* nx = sm + ((kt + 1) & 1) * GSTG;
            const int k0 = (kt + 1) * 32;
            cp16(nx + so,         Agh + arow + k0); cp16(nx + so + 8,         Agh + arow + k0 + 8);
            if (SPLIT) {
                cp16(nx + GBUF + so,     Agl + arow + k0);
                cp16(nx + GBUF + so + 8, Agl + arow + k0 + 8);
            }
            cp16(nx + BOFFB + so, Bgh + brow + k0); cp16(nx + BOFFB + so + 8, Bgh + brow + k0 + 8);
            CP_COMMIT();
        }

        const __half* Ah = sm + (kt & 1) * GSTG;
        const __half* Al = Ah + GBUF;
        const __half* Bh = Ah + BOFFB;

        #pragma unroll
        for (int ks = 0; ks < 2; ks++) {
            const int kk = ks * 16;
            unsigned ahi[2][4], alo[2][4];
            ldsm4(ahi[0], Ah + (wm     ) * SSTR + kk + aoff);
            ldsm4(ahi[1], Ah + (wm + 16) * SSTR + kk + aoff);
            if (SPLIT) {
                ldsm4(alo[0], Al + (wm     ) * SSTR + kk + aoff);
                ldsm4(alo[1], Al + (wm + 16) * SSTR + kk + aoff);
            }
            #pragma unroll
            for (int p = 0; p < 2; p++) {
                unsigned bh0[4], bh1[4];
                ldsm4(bh0, Bh + (wn + 32 * p     ) * SSTR + kk + boff);
                ldsm4(bh1, Bh + (wn + 32 * p + 16) * SSTR + kk + boff);
                const int j0 = 4 * p;
                mmaF(c[0][j0 + 0], ahi[0], bh0[0], bh0[1]);
                mmaF(c[1][j0 + 0], ahi[1], bh0[0], bh0[1]);
                mmaF(c[0][j0 + 1], ahi[0], bh0[2], bh0[3]);
                mmaF(c[1][j0 + 1], ahi[1], bh0[2], bh0[3]);
                mmaF(c[0][j0 + 2], ahi[0], bh1[0], bh1[1]);
                mmaF(c[1][j0 + 2], ahi[1], bh1[0], bh1[1]);
                mmaF(c[0][j0 + 3], ahi[0], bh1[2], bh1[3]);
                mmaF(c[1][j0 + 3], ahi[1], bh1[2], bh1[3]);
                if (SPLIT) {
                    mmaF(c[0][j0 + 0], alo[0], bh0[0], bh0[1]);
                    mmaF(c[1][j0 + 0], alo[1], bh0[0], bh0[1]);
                    mmaF(c[0][j0 + 1], alo[0], bh0[2], bh0[3]);
                    mmaF(c[1][j0 + 1], alo[1], bh0[2], bh0[3]);
                    mmaF(c[0][j0 + 2], alo[0], bh1[0], bh1[1]);
                    mmaF(c[1][j0 + 2], alo[1], bh1[0], bh1[1]);
                    mmaF(c[0][j0 + 3], alo[0], bh1[2], bh1[3]);
                    mmaF(c[1][j0 + 3], alo[1], bh1[2], bh1[3]);
                }
            }
        }
        CP_WAIT0();
        __syncthreads();
    }
}

// Fused QKV projection; blockIdx.z selects weight.
// Q -> split [b,h,s,d]; K -> single [b,h,s,d];
// V -> single [b,h,d,s], written COALESCED via smem transpose.
__global__ __launch_bounds__(256, 2) void gemm_qkv()
{
    extern __shared__ __half smg[];
    float c[2][8][4];
    #pragma unroll
    for (int i = 0; i < 2; i++)
        #pragma unroll
        for (int j = 0; j < 8; j++)
            #pragma unroll
            for (int q = 0; q < 4; q++) c[i][j][q] = 0.f;

    const int m0 = blockIdx.y * 128;
    const int n0 = blockIdx.x * 128;
    const int z  = blockIdx.z;

    gemm_hf_body<true>(g_xh, g_xl, g_wh[z], m0, n0, c, smg);

    const int tid  = threadIdx.x;
    const int lane = tid & 31;
    const int g = lane >> 2, t = lane & 3;
    const int warp = tid >> 5;
    const int wm = (warp >> 1) * 32, wn = (warp & 1) * 64;

    if (z == 2) {
        // ---- smem transpose: vs[n - n0][m - m0], stride 136 (16B-aligned rows)
        #define VS 136
        __half* vs = smg;
        #pragma unroll
        for (int i = 0; i < 2; i++) {
            #pragma unroll
            for (int j = 0; j < 8; j++) {
                const int nn = wn + 8 * j + 2 * t;
                const int mm = wm + 16 * i + g;
                vs[(nn    ) * VS + mm    ] = __float2half_rn(c[i][j][0]);
                vs[(nn + 1) * VS + mm    ] = __float2half_rn(c[i][j][1]);
                vs[(nn    ) * VS + mm + 8] = __float2half_rn(c[i][j][2]);
                vs[(nn + 1) * VS + mm + 8] = __float2half_rn(c[i][j][3]);
            }
        }
        __syncthreads();
        // ---- coalesced store: row = n (head*64+d), cols = 128 contiguous s
        const int r    = tid >> 1;             // 0..127
        const int cseg = (tid & 1) * 64;       // 0 / 64
        const int n = n0 + r;
        const int h = n >> 6, d = n & 63;
        const int b = m0 >> 11, s0 = m0 & 2047;
        __half* dst = g_vth + ((size_t)(b * NUM_HEADS + h) * D_HEAD + d) * SEQ + s0 + cseg;
        const __half* src = vs + r * VS + cseg;
        #pragma unroll
        for (int u = 0; u < 8; u++)
            *(uint4*)&dst[8 * u] = *(const uint4*)&src[8 * u];
        #undef VS
    } else {
        #pragma unroll
        for (int i = 0; i < 2; i++) {
            #pragma unroll
            for (int j = 0; j < 8; j++) {
                const int n = n0 + wn + 8 * j + 2 * t;
                const int h = n >> 6, d = n & 63;
                const int r0 = m0 + wm + 16 * i + g;
                const int r1 = r0 + 8;
                const int b0 = r0 >> 11, s0 = r0 & 2047;
                const int b1 = r1 >> 11, s1 = r1 & 2047;
                const size_t i0 = ((size_t)(b0 * NUM_HEADS + h) * SEQ + s0) * D_HEAD + d;
                const size_t i1 = ((size_t)(b1 * NUM_HEADS + h) * SEQ + s1) * D_HEAD + d;
                if (z == 0) {
                    __half h0, l0, h1, l1, h2, l2, h3, l3;
                    split_hf(c[i][j][0], h0, l0); split_hf(c[i][j][1], h1, l1);
                    split_hf(c[i][j][2], h2, l2); split_hf(c[i][j][3], h3, l3);
                    *(unsigned*)&g_qh[i0] = pk(h0, h1);
                    *(unsigned*)&g_ql[i0] = pk(l0, l1);
                    *(unsigned*)&g_qh[i1] = pk(h2, h3);
                    *(unsigned*)&g_ql[i1] = pk(l2, l3);
                } else {
                    *(unsigned*)&g_kh[i0] = pk(__float2half_rn(c[i][j][0]),
                                               __float2half_rn(c[i][j][1]));
                    *(unsigned*)&g_kh[i1] = pk(__float2half_rn(c[i][j][2]),
                                               __float2half_rn(c[i][j][3]));
                }
            }
        }
    }
}

// Output projection: out = ctx(single) @ Ow^T, fp32 out. 1-term GEMM.
__global__ __launch_bounds__(256, 2) void gemm_out(float* __restrict__ out)
{
    extern __shared__ __half smg[];
    float c[2][8][4];
    #pragma unroll
    for (int i = 0; i < 2; i++)
        #pragma unroll
        for (int j = 0; j < 8; j++)
            #pragma unroll
            for (int q = 0; q < 4; q++) c[i][j][q] = 0.f;

    const int m0 = blockIdx.y * 128;
    const int n0 = blockIdx.x * 128;

    gemm_hf_body<false>(g_ch, nullptr, g_wh[3], m0, n0, c, smg);

    const int lane = threadIdx.x & 31;
    const int g = lane >> 2, t = lane & 3;
    const int warp = threadIdx.x >> 5;
    const int wm = (warp >> 1) * 32, wn = (warp & 1) * 64;

    #pragma unroll
    for (int i = 0; i < 2; i++) {
        #pragma unroll
        for (int j = 0; j < 8; j++) {
            const int n  = n0 + wn + 8 * j + 2 * t;
            const int r0 = m0 + wm + 16 * i + g;
            *(float2*)&out[(size_t)r0 * D_MODEL + n] = make_float2(c[i][j][0], c[i][j][1]);
            *(float2*)&out[(size_t)(r0 + 8) * D_MODEL + n] = make_float2(c[i][j][2], c[i][j][3]);
        }
    }
}

// ---------------- Flash attention: Q split; K,V,P,ctx single -----------------
// Block = (b, h, 128-q-tile). 256 threads = 8 warps. KV tiles of 64.
#define QSTR 72
#define TILEC (64 * QSTR)
#define ATTN_SMEM (6 * TILEC * 2)         // 55296 bytes: 2 KV stages + Ph

__global__ __launch_bounds__(256, 2) void attn_mma(const unsigned char* __restrict__ pm)
{
    extern __shared__ __half smb[];
    __half* stg0 = smb;                   // {Kh, Vth} stage 0
    __half* stg1 = smb + 2 * TILEC;       // stage 1
    __half* Ph   = smb + 4 * TILEC;       // P single (128 rows)

    const int qt = gridDim.x - 1 - blockIdx.x;
    const int h  = blockIdx.y;
    const int b  = blockIdx.z;
    const int tid  = threadIdx.x;
    const int lane = tid & 31;
    const int warp = tid >> 5;
    const int g = lane >> 2, t = lane & 3;
    const size_t base = (size_t)(b * NUM_HEADS + h) * SEQ;

    const int rw = warp * 16;
    const int Rg = qt * 128 + rw;
    const int kt_max = 2 * qt + 1;

    const int aoffQ = ((lane & 7) + ((lane >> 3) & 1) * 8) * QSTR + (lane >> 4) * 8;
    const int boffQ = ((lane & 7) + (lane >> 4) * 8) * QSTR + ((lane >> 3) & 1) * 8;

    const int krow = tid >> 2;
    const int kcs  = (tid & 3) * 16;
    const int kso  = krow * QSTR + kcs;
    const size_t vbase = ((size_t)(b * NUM_HEADS + h) * D_HEAD + krow) * SEQ + kcs;
    const size_t kbase = (base + krow) * D_HEAD + kcs;

    // ---- stage Q split (hi in [0,2T), lo in [2T,4T)), move to regs ----
    {
        const int row = tid >> 1, cs = (tid & 1) * 32;
        const size_t ga = (base + (size_t)qt * 128 + row) * D_HEAD + cs;
        const int so = row * QSTR + cs;
        #pragma unroll
        for (int u = 0; u < 4; u++) {
            cp16(&smb[so + 8 * u],             &g_qh[ga + 8 * u]);
            cp16(&smb[2 * TILEC + so + 8 * u], &g_ql[ga + 8 * u]);
        }
        CP_COMMIT();
        CP_WAIT0();
    }
    __syncthreads();

    unsigned qh[4][4], ql[4][4];
    #pragma unroll
    for (int ks = 0; ks < 4; ks++) {
        ldsm4(qh[ks], smb + rw * QSTR + 16 * ks + aoffQ);
        ldsm4(ql[ks], smb + 2 * TILEC + rw * QSTR + 16 * ks + aoffQ);
    }
    __syncthreads();                      // smem free for KV stages

    // ---- prologue: KV(0) into stg0 ----
    {
        cp16(&stg0[kso],         &g_kh[kbase]);  cp16(&stg0[kso + 8],         &g_kh[kbase + 8]);
        cp16(&stg0[TILEC + kso], &g_vth[vbase]); cp16(&stg0[TILEC + kso + 8], &g_vth[vbase + 8]);
        CP_COMMIT();
    }

    float o[8][4];
    float m_i[2] = {-1e30f, -1e30f};
    float l_i[2] = {0.f, 0.f};
    #pragma unroll
    for (int j = 0; j < 8; j++)
        #pragma unroll
        for (int q = 0; q < 4; q++) o[j][q] = 0.f;

    for (int kt = 0; kt <= kt_max; kt++) {
        if (kt < kt_max) {
            __half* nx = ((kt + 1) & 1) ? stg1 : stg0;
            const size_t gk = kbase + (size_t)(kt + 1) * 64 * D_HEAD;
            const size_t gv = vbase + (size_t)(kt + 1) * 64;
            cp16(&nx[kso],         &g_kh[gk]);  cp16(&nx[kso + 8],         &g_kh[gk + 8]);
            cp16(&nx[TILEC + kso], &g_vth[gv]); cp16(&nx[TILEC + kso + 8], &g_vth[gv + 8]);
            CP_COMMIT();
            CP_WAIT1();                    // KV(kt) complete
        } else {
            CP_WAIT0();
        }
        __syncthreads();

        const int C0 = kt * 64;
        if (C0 <= Rg + 15) {
            const __half* Kh = (kt & 1) ? stg1 : stg0;
            const __half* Vh = Kh + TILEC;

            float s[8][4];
            #pragma unroll
            for (int j = 0; j < 8; j++)
                #pragma unroll
                for (int q = 0; q < 4; q++) s[j][q] = 0.f;

            // ---- S = (Qhi + Qlo) @ Kh^T ----
            #pragma unroll
            for (int ks = 0; ks < 4; ks++) {
                const int kk = 16 * ks;
                #pragma unroll
                for (int p = 0; p < 2; p++) {
                    unsigned bh0[4], bh1[4];
                    ldsm4(bh0, Kh + (32 * p     ) * QSTR + kk + boffQ);
                    ldsm4(bh1, Kh + (32 * p + 16) * QSTR + kk + boffQ);
                    const int j0 = 4 * p;
                    mmaF(s[j0 + 0], qh[ks], bh0[0], bh0[1]);
                    mmaF(s[j0 + 1], qh[ks], bh0[2], bh0[3]);
                    mmaF(s[j0 + 2], qh[ks], bh1[0], bh1[1]);
                    mmaF(s[j0 + 3], qh[ks], bh1[2], bh1[3]);
                    mmaF(s[j0 + 0], ql[ks], bh0[0], bh0[1]);
                    mmaF(s[j0 + 1], ql[ks], bh0[2], bh0[3]);
                    mmaF(s[j0 + 2], ql[ks], bh1[0], bh1[1]);
                    mmaF(s[j0 + 3], ql[ks], bh1[2], bh1[3]);
                }
            }

            // ---- scale (log2 domain) + causal + padding masks ----
            const unsigned char* pmb = pm + (size_t)b * SEQ + C0;
            const int r0 = Rg + g, r1 = r0 + 8;
            #pragma unroll
            for (int j = 0; j < 8; j++) {
                const int c0 = C0 + 8 * j + 2 * t, c1 = c0 + 1;
                const bool p0 = pmb[8 * j + 2 * t] != 0;
                const bool p1 = pmb[8 * j + 2 * t + 1] != 0;
                float v;
                v = s[j][0] * SCALE_LOG2E; if (c0 > r0 || p0) v = -1e30f; s[j][0] = v;
                v = s[j][1] * SCALE_LOG2E; if (c1 > r0 || p1) v = -1e30f; s[j][1] = v;
                v = s[j][2] * SCALE_LOG2E; if (c0 > r1 || p0) v = -1e30f; s[j][2] = v;
                v = s[j][3] * SCALE_LOG2E; if (c1 > r1 || p1) v = -1e30f; s[j][3] = v;
            }

            // ---- online softmax, base-2, FMA-pipe exp ----
            #pragma unroll
            for (int rr = 0; rr < 2; rr++) {
                float rm = -1e30f;
                #pragma unroll
                for (int j = 0; j < 8; j++)
                    rm = fmaxf(rm, fmaxf(s[j][2 * rr], s[j][2 * rr + 1]));
                rm = fmaxf(rm, __shfl_xor_sync(0xffffffffu, rm, 1));
                rm = fmaxf(rm, __shfl_xor_sync(0xffffffffu, rm, 2));
                const float mn    = fmaxf(m_i[rr], rm);
                const float alpha = exp2_fast(m_i[rr] - mn);
                m_i[rr] = mn;
                float rs = 0.f;
                #pragma unroll
                for (int j = 0; j < 8; j++) {
                    s[j][2 * rr    ] = exp2_fast(s[j][2 * rr    ] - mn);
                    s[j][2 * rr + 1] = exp2_fast(s[j][2 * rr + 1] - mn);
                    rs += s[j][2 * rr] + s[j][2 * rr + 1];
                }
                rs += __shfl_xor_sync(0xffffffffu, rs, 1);
                rs += __shfl_xor_sync(0xffffffffu, rs, 2);
                l_i[rr] = l_i[rr] * alpha + rs;
                #pragma unroll
                for (int j = 0; j < 8; j++) {
                    o[j][2 * rr    ] *= alpha;
                    o[j][2 * rr + 1] *= alpha;
                }
            }

            // ---- write P single (warp-private rows) ----
            #pragma unroll
            for (int j = 0; j < 8; j++) {
                const int p0 = (rw + g) * QSTR + 8 * j + 2 * t;
                const int p1 = p0 + 8 * QSTR;
                *(unsigned*)&Ph[p0] = pk(__float2half_rn(s[j][0]),
                                         __float2half_rn(s[j][1]));
                *(unsigned*)&Ph[p1] = pk(__float2half_rn(s[j][2]),
                                         __float2half_rn(s[j][3]));
            }
            __syncwarp();

            // ---- O += P @ Vh (1-term) ----
            #pragma unroll
            for (int ks = 0; ks < 4; ks++) {
                const int kk = 16 * ks;
                unsigned ph[4];
                ldsm4(ph, Ph + rw * QSTR + kk + aoffQ);
                #pragma unroll
                for (int p = 0; p < 2; p++) {
                    unsigned bh0[4], bh1[4];
                    ldsm4(bh0, Vh + (32 * p     ) * QSTR + kk + boffQ);
                    ldsm4(bh1, Vh + (32 * p + 16) * QSTR + kk + boffQ);
                    const int j0 = 4 * p;
                    mmaF(o[j0 + 0], ph, bh0[0], bh0[1]);
                    mmaF(o[j0 + 1], ph, bh0[2], bh0[3]);
                    mmaF(o[j0 + 2], ph, bh1[0], bh1[1]);
                    mmaF(o[j0 + 3], ph, bh1[2], bh1[3]);
                }
            }
        }
        __syncthreads();
    }

    // ---- normalize + write ctx single [b, s, h*64 + col] ----
    const float inv0 = 1.f / l_i[0];
    const float inv1 = 1.f / l_i[1];
    const int row0 = qt * 128 + rw + g;
    const size_t d0 = ((size_t)b * SEQ + row0    ) * D_MODEL + h * D_HEAD;
    const size_t d1 = ((size_t)b * SEQ + row0 + 8) * D_MODEL + h * D_HEAD;
    #pragma unroll
    for (int j = 0; j < 8; j++) {
        const int cidx = 8 * j + 2 * t;
        *(unsigned*)&g_ch[d0 + cidx] = pk(__float2half_rn(o[j][0] * inv0),
                                          __float2half_rn(o[j][1] * inv0));
        *(unsigned*)&g_ch[d1 + cidx] = pk(__float2half_rn(o[j][2] * inv1),
                                          __float2half_rn(o[j][3] * inv1));
    }
}

// ---------------- launch ----------------------------------------------------
extern "C" void kernel_launch(void* const* d_in, const int* in_sizes, int n_in,
                              void* d_out, int out_size)
{
    (void)in_sizes; (void)n_in; (void)out_size;
    const float* x  = (const float*)d_in[0];
    const float* Qw = (const float*)d_in[1];
    const float* Kw = (const float*)d_in[2];
    const float* Vw = (const float*)d_in[3];
    const float* Ow = (const float*)d_in[4];
    const unsigned char* pm = (const unsigned char*)d_in[5];
    float* out = (float*)d_out;

    cudaFuncSetAttribute(attn_mma, cudaFuncAttributeMaxDynamicSharedMemorySize, ATTN_SMEM);
    cudaFuncSetAttribute(gemm_qkv, cudaFuncAttributeMaxDynamicSharedMemorySize, GEMM_SMEM_SPLIT);
    cudaFuncSetAttribute(gemm_out, cudaFuncAttributeMaxDynamicSharedMemorySize, GEMM_SMEM_SINGLE);

    split_all<<<12288, 256>>>(x, Qw, Kw, Vw, Ow);

    dim3 gq(D_MODEL / 128, MTOT / 128, 3);        // 8 x 64 x 3
    gemm_qkv<<<gq, 256, GEMM_SMEM_SPLIT>>>();

    dim3 ga(SEQ / 128, NUM_HEADS, BATCH);         // 16 x 16 x 4
    attn_mma<<<ga, 256, ATTN_SMEM>>>(pm);

    dim3 go(D_MODEL / 128, MTOT / 128);           // 8 x 64
    gemm_out<<<go, 256, GEMM_SMEM_SINGLE>>>(out);
}

// round 12
// speedup vs baseline: 2.1642x; 1.1272x over previous
#include <cuda_runtime.h>
#include <cuda_fp16.h>
#include <cstdint>

#define D_MODEL   1024
#define NUM_HEADS 16
#define D_HEAD    64
#define BATCH     4
#define SEQ       2048
#define MTOT      (BATCH * SEQ)   // 8192
#define QKV_EL    (BATCH * NUM_HEADS * SEQ * D_HEAD)   // 8388608

// ---------------- scratch (device globals: allocation-guard safe) ----------
__device__ __half g_xh[MTOT * D_MODEL],  g_xl[MTOT * D_MODEL];
__device__ __half g_wh[4][D_MODEL * D_MODEL];          // weights: single fp16
__device__ __half g_qh[QKV_EL], g_ql[QKV_EL];          // [b,h,s,d] split
__device__ __half g_kh[QKV_EL];                        // [b,h,s,d] single
__device__ __half g_vth[QKV_EL];                       // [b,h,d,s] single
__device__ __half g_ch[MTOT * D_MODEL];                // ctx single

// ---------------- helpers ----------------------------------------------------
__device__ __forceinline__ void split_hf(float x, __half& h, __half& l) {
    h = __float2half_rn(x);
    l = __float2half_rn(x - __half2float(h));
}
__device__ __forceinline__ unsigned pk(__half a, __half b) {
    return (unsigned)__half_as_ushort(a) | ((unsigned)__half_as_ushort(b) << 16);
}
__device__ __forceinline__ void split_store4(float4 v, __half* hp, __half* lp) {
    __half h0, l0, h1, l1, h2, l2, h3, l3;
    split_hf(v.x, h0, l0); split_hf(v.y, h1, l1);
    split_hf(v.z, h2, l2); split_hf(v.w, h3, l3);
    *(uint2*)hp = make_uint2(pk(h0, h1), pk(h2, h3));
    *(uint2*)lp = make_uint2(pk(l0, l1), pk(l2, l3));
}
__device__ __forceinline__ void round_store4(float4 v, __half* hp) {
    *(uint2*)hp = make_uint2(pk(__float2half_rn(v.x), __float2half_rn(v.y)),
                             pk(__float2half_rn(v.z), __float2half_rn(v.w)));
}
// fp32-accumulator mma (fp16 inputs)
__device__ __forceinline__ void mmaF(float* c, const unsigned* a, unsigned b0, unsigned b1) {
    asm volatile(
        "mma.sync.aligned.m16n8k16.row.col.f32.f16.f16.f32 "
        "{%0,%1,%2,%3}, {%4,%5,%6,%7}, {%8,%9}, {%0,%1,%2,%3};"
        : "+f"(c[0]), "+f"(c[1]), "+f"(c[2]), "+f"(c[3])
        : "r"(a[0]), "r"(a[1]), "r"(a[2]), "r"(a[3]), "r"(b0), "r"(b1));
}
__device__ __forceinline__ void ldsm4(unsigned r[4], const __half* p) {
    unsigned a = (unsigned)__cvta_generic_to_shared(p);
    asm volatile("ldmatrix.sync.aligned.m8n8.x4.shared.b16 {%0,%1,%2,%3}, [%4];"
                 : "=r"(r[0]), "=r"(r[1]), "=r"(r[2]), "=r"(r[3]) : "r"(a));
}
__device__ __forceinline__ void cp16(__half* s, const __half* g) {
    unsigned sa = (unsigned)__cvta_generic_to_shared(s);
    asm volatile("cp.async.cg.shared.global [%0], [%1], 16;" :: "r"(sa), "l"(g));
}
#define CP_COMMIT() asm volatile("cp.async.commit_group;")
#define CP_WAIT0()  asm volatile("cp.async.wait_group 0;")
#define CP_WAIT1()  asm volatile("cp.async.wait_group 1;")

// fast exp2 on the FMA pipe (MUFU-free)
__device__ __forceinline__ float exp2_fast(float y) {
    y = fmaxf(y, -120.f);
    float z = y + 12582912.f;
    int   e = __float_as_int(z);
    float f = y - (z - 12582912.f);
    float p = 1.f + f * (0.6931471805599453f + f * (0.2402265069591007f +
              f * (0.0555041086648216f + f * (0.0096181291076285f +
              f * 0.0013333558146429f))));
    return __int_as_float(__float_as_int(p) + (e << 23));
}
#define SCALE_LOG2E 0.18033688011112042f   // 0.125 * log2(e)

// ---------------- one-shot split of x + round of weights ---------------------
__global__ __launch_bounds__(256) void split_all(const float* __restrict__ x,
                                                 const float* __restrict__ Qw,
                                                 const float* __restrict__ Kw,
                                                 const float* __restrict__ Vw,
                                                 const float* __restrict__ Ow)
{
    const int idx = blockIdx.x * 256 + threadIdx.x;        // one float4 each
    if (idx < 2097152) {
        float4 v = ((const float4*)x)[idx];
        split_store4(v, g_xh + (size_t)idx * 4, g_xl + (size_t)idx * 4);
    } else {
        const int w = (idx - 2097152) >> 18;
        const size_t off = (size_t)((idx - 2097152) & 262143);
        const float* src = (w == 0) ? Qw : (w == 1) ? Kw : (w == 2) ? Vw : Ow;
        float4 v = ((const float4*)src)[off];
        round_store4(v, g_wh[w] + off * 4);
    }
}

// ---------------- fp16 GEMM body, templated on A-split -----------------------
// Block tile 128x128, BK=32, 256 threads = 8 warps (4m x 2n), warp tile 32x64.
#define SSTR 40
#define GBUF (128 * SSTR)
#define GEMM_SMEM_SPLIT  (2 * 3 * GBUF * 2)   // 61440 bytes (Ah, Al, Bh) x2
#define GEMM_SMEM_SINGLE (2 * 2 * GBUF * 2)   // 40960 bytes (Ah, Bh) x2

template<bool SPLIT>
__device__ __forceinline__ void gemm_hf_body(const __half* __restrict__ Agh,
                                             const __half* __restrict__ Agl,
                                             const __half* __restrict__ Bgh,
                                             int m0, int n0,
                                             float (&c)[2][8][4],
                                             __half* sm)
{
    constexpr int NT   = SPLIT ? 3 : 2;
    constexpr int GSTG = NT * GBUF;
    constexpr int BOFFB = (NT - 1) * GBUF;     // Bh tile offset within stage

    const int tid  = threadIdx.x;
    const int lane = tid & 31;
    const int warp = tid >> 5;
    const int wm   = (warp >> 1) * 32;
    const int wn   = (warp & 1) * 64;
    const int lrow = tid >> 1;
    const int lcol = (tid & 1) * 16;
    const int so   = lrow * SSTR + lcol;

    const int aoff = ((lane & 7) + ((lane >> 3) & 1) * 8) * SSTR + (lane >> 4) * 8;
    const int boff = ((lane & 7) + (lane >> 4) * 8) * SSTR + ((lane >> 3) & 1) * 8;

    const size_t arow = (size_t)(m0 + lrow) * D_MODEL + lcol;
    const size_t brow = (size_t)(n0 + lrow) * D_MODEL + lcol;

    {   // prologue: stage 0 <- k-tile 0
        __half* st = sm;
        cp16(st + so,         Agh + arow); cp16(st + so + 8,         Agh + arow + 8);
        if (SPLIT) {
            cp16(st + GBUF + so,     Agl + arow);
            cp16(st + GBUF + so + 8, Agl + arow + 8);
        }
        cp16(st + BOFFB + so, Bgh + brow); cp16(st + BOFFB + so + 8, Bgh + brow + 8);
        CP_COMMIT();
        CP_WAIT0();
    }
    __syncthreads();

    for (int kt = 0; kt < 32; kt++) {
        if (kt + 1 < 32) {
            __half* nx = sm + ((kt + 1) & 1) * GSTG;
            const int k0 = (kt + 1) * 32;
            cp16(nx + so,         Agh + arow + k0); cp16(nx + so + 8,         Agh + arow + k0 + 8);
            if (SPLIT) {
                cp16(nx + GBUF + so,     Agl + arow + k0);
                cp16(nx + GBUF + so + 8, Agl + arow + k0 + 8);
            }
            cp16(nx + BOFFB + so, Bgh + brow + k0); cp16(nx + BOFFB + so + 8, Bgh + brow + k0 + 8);
            CP_COMMIT();
        }

        const __half* Ah = sm + (kt & 1) * GSTG;
        const __half* Al = Ah + GBUF;
        const __half* Bh = Ah + BOFFB;

        #pragma unroll
        for (int ks = 0; ks < 2; ks++) {
            const int kk = ks * 16;
            unsigned ahi[2][4], alo[2][4];
            ldsm4(ahi[0], Ah + (wm     ) * SSTR + kk + aoff);
            ldsm4(ahi[1], Ah + (wm + 16) * SSTR + kk + aoff);
            if (SPLIT) {
                ldsm4(alo[0], Al + (wm     ) * SSTR + kk + aoff);
                ldsm4(alo[1], Al + (wm + 16) * SSTR + kk + aoff);
            }
            #pragma unroll
            for (int p = 0; p < 2; p++) {
                unsigned bh0[4], bh1[4];
                ldsm4(bh0, Bh + (wn + 32 * p     ) * SSTR + kk + boff);
                ldsm4(bh1, Bh + (wn + 32 * p + 16) * SSTR + kk + boff);
                const int j0 = 4 * p;
                mmaF(c[0][j0 + 0], ahi[0], bh0[0], bh0[1]);
                mmaF(c[1][j0 + 0], ahi[1], bh0[0], bh0[1]);
                mmaF(c[0][j0 + 1], ahi[0], bh0[2], bh0[3]);
                mmaF(c[1][j0 + 1], ahi[1], bh0[2], bh0[3]);
                mmaF(c[0][j0 + 2], ahi[0], bh1[0], bh1[1]);
                mmaF(c[1][j0 + 2], ahi[1], bh1[0], bh1[1]);
                mmaF(c[0][j0 + 3], ahi[0], bh1[2], bh1[3]);
                mmaF(c[1][j0 + 3], ahi[1], bh1[2], bh1[3]);
                if (SPLIT) {
                    mmaF(c[0][j0 + 0], alo[0], bh0[0], bh0[1]);
                    mmaF(c[1][j0 + 0], alo[1], bh0[0], bh0[1]);
                    mmaF(c[0][j0 + 1], alo[0], bh0[2], bh0[3]);
                    mmaF(c[1][j0 + 1], alo[1], bh0[2], bh0[3]);
                    mmaF(c[0][j0 + 2], alo[0], bh1[0], bh1[1]);
                    mmaF(c[1][j0 + 2], alo[1], bh1[0], bh1[1]);
                    mmaF(c[0][j0 + 3], alo[0], bh1[2], bh1[3]);
                    mmaF(c[1][j0 + 3], alo[1], bh1[2], bh1[3]);
                }
            }
        }
        CP_WAIT0();
        __syncthreads();
    }
}

// Fused QKV projection; blockIdx.z selects weight.
// Q (z=0): 2-term split-x GEMM -> split [b,h,s,d].
// K (z=1): 1-term x-hi GEMM   -> single [b,h,s,d]   (K is fp16-rounded anyway).
// V (z=2): 1-term x-hi GEMM   -> single [b,h,d,s], coalesced via smem transpose.
__global__ __launch_bounds__(256, 2) void gemm_qkv()
{
    extern __shared__ __half smg[];
    float c[2][8][4];
    #pragma unroll
    for (int i = 0; i < 2; i++)
        #pragma unroll
        for (int j = 0; j < 8; j++)
            #pragma unroll
            for (int q = 0; q < 4; q++) c[i][j][q] = 0.f;

    const int m0 = blockIdx.y * 128;
    const int n0 = blockIdx.x * 128;
    const int z  = blockIdx.z;

    if (z == 0) gemm_hf_body<true >(g_xh, g_xl,    g_wh[z], m0, n0, c, smg);
    else        gemm_hf_body<false>(g_xh, nullptr, g_wh[z], m0, n0, c, smg);

    const int tid  = threadIdx.x;
    const int lane = tid & 31;
    const int g = lane >> 2, t = lane & 3;
    const int warp = tid >> 5;
    const int wm = (warp >> 1) * 32, wn = (warp & 1) * 64;

    if (z == 2) {
        // ---- smem transpose: vs[n - n0][m - m0], stride 136 (16B-aligned rows)
        #define VS 136
        __half* vs = smg;
        __syncthreads();   // mainloop done with smem everywhere before reuse
        #pragma unroll
        for (int i = 0; i < 2; i++) {
            #pragma unroll
            for (int j = 0; j < 8; j++) {
                const int nn = wn + 8 * j + 2 * t;
                const int mm = wm + 16 * i + g;
                vs[(nn    ) * VS + mm    ] = __float2half_rn(c[i][j][0]);
                vs[(nn + 1) * VS + mm    ] = __float2half_rn(c[i][j][1]);
                vs[(nn    ) * VS + mm + 8] = __float2half_rn(c[i][j][2]);
                vs[(nn + 1) * VS + mm + 8] = __float2half_rn(c[i][j][3]);
            }
        }
        __syncthreads();
        // ---- coalesced store: row = n (head*64+d), cols = 128 contiguous s
        const int r    = tid >> 1;             // 0..127
        const int cseg = (tid & 1) * 64;       // 0 / 64
        const int n = n0 + r;
        const int h = n >> 6, d = n & 63;
        const int b = m0 >> 11, s0 = m0 & 2047;
        __half* dst = g_vth + ((size_t)(b * NUM_HEADS + h) * D_HEAD + d) * SEQ + s0 + cseg;
        const __half* src = vs + r * VS + cseg;
        #pragma unroll
        for (int u = 0; u < 8; u++)
            *(uint4*)&dst[8 * u] = *(const uint4*)&src[8 * u];
        #undef VS
    } else {
        #pragma unroll
        for (int i = 0; i < 2; i++) {
            #pragma unroll
            for (int j = 0; j < 8; j++) {
                const int n = n0 + wn + 8 * j + 2 * t;
                const int h = n >> 6, d = n & 63;
                const int r0 = m0 + wm + 16 * i + g;
                const int r1 = r0 + 8;
                const int b0 = r0 >> 11, s0 = r0 & 2047;
                const int b1 = r1 >> 11, s1 = r1 & 2047;
                const size_t i0 = ((size_t)(b0 * NUM_HEADS + h) * SEQ + s0) * D_HEAD + d;
                const size_t i1 = ((size_t)(b1 * NUM_HEADS + h) * SEQ + s1) * D_HEAD + d;
                if (z == 0) {
                    __half h0, l0, h1, l1, h2, l2, h3, l3;
                    split_hf(c[i][j][0], h0, l0); split_hf(c[i][j][1], h1, l1);
                    split_hf(c[i][j][2], h2, l2); split_hf(c[i][j][3], h3, l3);
                    *(unsigned*)&g_qh[i0] = pk(h0, h1);
                    *(unsigned*)&g_ql[i0] = pk(l0, l1);
                    *(unsigned*)&g_qh[i1] = pk(h2, h3);
                    *(unsigned*)&g_ql[i1] = pk(l2, l3);
                } else {
                    *(unsigned*)&g_kh[i0] = pk(__float2half_rn(c[i][j][0]),
                                               __float2half_rn(c[i][j][1]));
                    *(unsigned*)&g_kh[i1] = pk(__float2half_rn(c[i][j][2]),
                                               __float2half_rn(c[i][j][3]));
                }
            }
        }
    }
}

// Output projection: out = ctx(single) @ Ow^T, fp32 out. 1-term GEMM.
__global__ __launch_bounds__(256, 2) void gemm_out(float* __restrict__ out)
{
    extern __shared__ __half smg[];
    float c[2][8][4];
    #pragma unroll
    for (int i = 0; i < 2; i++)
        #pragma unroll
        for (int j = 0; j < 8; j++)
            #pragma unroll
            for (int q = 0; q < 4; q++) c[i][j][q] = 0.f;

    const int m0 = blockIdx.y * 128;
    const int n0 = blockIdx.x * 128;

    gemm_hf_body<false>(g_ch, nullptr, g_wh[3], m0, n0, c, smg);

    const int lane = threadIdx.x & 31;
    const int g = lane >> 2, t = lane & 3;
    const int warp = threadIdx.x >> 5;
    const int wm = (warp >> 1) * 32, wn = (warp & 1) * 64;

    #pragma unroll
    for (int i = 0; i < 2; i++) {
        #pragma unroll
        for (int j = 0; j < 8; j++) {
            const int n  = n0 + wn + 8 * j + 2 * t;
            const int r0 = m0 + wm + 16 * i + g;
            *(float2*)&out[(size_t)r0 * D_MODEL + n] = make_float2(c[i][j][0], c[i][j][1]);
            *(float2*)&out[(size_t)(r0 + 8) * D_MODEL + n] = make_float2(c[i][j][2], c[i][j][3]);
        }
    }
}

// ---------------- Flash attention: Q split; K,V,P,ctx single -----------------
// Block = (b, h, 128-q-tile). 256 threads = 8 warps. KV tiles of 64.
#define QSTR 72
#define TILEC (64 * QSTR)
#define ATTN_SMEM (6 * TILEC * 2)         // 55296 bytes: 2 KV stages + Ph

__global__ __launch_bounds__(256, 2) void attn_mma(const unsigned char* __restrict__ pm)
{
    extern __shared__ __half smb[];
    __half* stg0 = smb;                   // {Kh, Vth} stage 0
    __half* stg1 = smb + 2 * TILEC;       // stage 1
    __half* Ph   = smb + 4 * TILEC;       // P single (128 rows)

    const int qt = gridDim.x - 1 - blockIdx.x;
    const int h  = blockIdx.y;
    const int b  = blockIdx.z;
    const int tid  = threadIdx.x;
    const int lane = tid & 31;
    const int warp = tid >> 5;
    const int g = lane >> 2, t = lane & 3;
    const size_t base = (size_t)(b * NUM_HEADS + h) * SEQ;

    const int rw = warp * 16;
    const int Rg = qt * 128 + rw;
    const int kt_max = 2 * qt + 1;

    const int aoffQ = ((lane & 7) + ((lane >> 3) & 1) * 8) * QSTR + (lane >> 4) * 8;
    const int boffQ = ((lane & 7) + (lane >> 4) * 8) * QSTR + ((lane >> 3) & 1) * 8;

    const int krow = tid >> 2;
    const int kcs  = (tid & 3) * 16;
    const int kso  = krow * QSTR + kcs;
    const size_t vbase = ((size_t)(b * NUM_HEADS + h) * D_HEAD + krow) * SEQ + kcs;
    const size_t kbase = (base + krow) * D_HEAD + kcs;

    // ---- stage Q split (hi in [0,2T), lo in [2T,4T)), move to regs ----
    {
        const int row = tid >> 1, cs = (tid & 1) * 32;
        const size_t ga = (base + (size_t)qt * 128 + row) * D_HEAD + cs;
        const int so = row * QSTR + cs;
        #pragma unroll
        for (int u = 0; u < 4; u++) {
            cp16(&smb[so + 8 * u],             &g_qh[ga + 8 * u]);
            cp16(&smb[2 * TILEC + so + 8 * u], &g_ql[ga + 8 * u]);
        }
        CP_COMMIT();
        CP_WAIT0();
    }
    __syncthreads();

    unsigned qh[4][4], ql[4][4];
    #pragma unroll
    for (int ks = 0; ks < 4; ks++) {
        ldsm4(qh[ks], smb + rw * QSTR + 16 * ks + aoffQ);
        ldsm4(ql[ks], smb + 2 * TILEC + rw * QSTR + 16 * ks + aoffQ);
    }
    __syncthreads();                      // smem free for KV stages

    // ---- prologue: KV(0) into stg0 ----
    {
        cp16(&stg0[kso],         &g_kh[kbase]);  cp16(&stg0[kso + 8],         &g_kh[kbase + 8]);
        cp16(&stg0[TILEC + kso], &g_vth[vbase]); cp16(&stg0[TILEC + kso + 8], &g_vth[vbase + 8]);
        CP_COMMIT();
    }

    float o[8][4];
    float m_i[2] = {-1e30f, -1e30f};
    float l_i[2] = {0.f, 0.f};
    #pragma unroll
    for (int j = 0; j < 8; j++)
        #pragma unroll
        for (int q = 0; q < 4; q++) o[j][q] = 0.f;

    for (int kt = 0; kt <= kt_max; kt++) {
        if (kt < kt_max) {
            __half* nx = ((kt + 1) & 1) ? stg1 : stg0;
            const size_t gk = kbase + (size_t)(kt + 1) * 64 * D_HEAD;
            const size_t gv = vbase + (size_t)(kt + 1) * 64;
            cp16(&nx[kso],         &g_kh[gk]);  cp16(&nx[kso + 8],         &g_kh[gk + 8]);
            cp16(&nx[TILEC + kso], &g_vth[gv]); cp16(&nx[TILEC + kso + 8], &g_vth[gv + 8]);
            CP_COMMIT();
            CP_WAIT1();                    // KV(kt) complete
        } else {
            CP_WAIT0();
        }
        __syncthreads();

        const int C0 = kt * 64;
        if (C0 <= Rg + 15) {
            const __half* Kh = (kt & 1) ? stg1 : stg0;
            const __half* Vh = Kh + TILEC;

            float s[8][4];
            #pragma unroll
            for (int j = 0; j < 8; j++)
                #pragma unroll
                for (int q = 0; q < 4; q++) s[j][q] = 0.f;

            // ---- S = (Qhi + Qlo) @ Kh^T ----
            #pragma unroll
            for (int ks = 0; ks < 4; ks++) {
                const int kk = 16 * ks;
                #pragma unroll
                for (int p = 0; p < 2; p++) {
                    unsigned bh0[4], bh1[4];
                    ldsm4(bh0, Kh + (32 * p     ) * QSTR + kk + boffQ);
                    ldsm4(bh1, Kh + (32 * p + 16) * QSTR + kk + boffQ);
                    const int j0 = 4 * p;
                    mmaF(s[j0 + 0], qh[ks], bh0[0], bh0[1]);
                    mmaF(s[j0 + 1], qh[ks], bh0[2], bh0[3]);
                    mmaF(s[j0 + 2], qh[ks], bh1[0], bh1[1]);
                    mmaF(s[j0 + 3], qh[ks], bh1[2], bh1[3]);
                    mmaF(s[j0 + 0], ql[ks], bh0[0], bh0[1]);
                    mmaF(s[j0 + 1], ql[ks], bh0[2], bh0[3]);
                    mmaF(s[j0 + 2], ql[ks], bh1[0], bh1[1]);
                    mmaF(s[j0 + 3], ql[ks], bh1[2], bh1[3]);
                }
            }

            // ---- scale (log2 domain) + causal + padding masks ----
            const unsigned char* pmb = pm + (size_t)b * SEQ + C0;
            const int r0 = Rg + g, r1 = r0 + 8;
            #pragma unroll
            for (int j = 0; j < 8; j++) {
                const int c0 = C0 + 8 * j + 2 * t, c1 = c0 + 1;
                const bool p0 = pmb[8 * j + 2 * t] != 0;
                const bool p1 = pmb[8 * j + 2 * t + 1] != 0;
                float v;
                v = s[j][0] * SCALE_LOG2E; if (c0 > r0 || p0) v = -1e30f; s[j][0] = v;
                v = s[j][1] * SCALE_LOG2E; if (c1 > r0 || p1) v = -1e30f; s[j][1] = v;
                v = s[j][2] * SCALE_LOG2E; if (c0 > r1 || p0) v = -1e30f; s[j][2] = v;
                v = s[j][3] * SCALE_LOG2E; if (c1 > r1 || p1) v = -1e30f; s[j][3] = v;
            }

            // ---- online softmax, base-2, FMA-pipe exp ----
            #pragma unroll
            for (int rr = 0; rr < 2; rr++) {
                float rm = -1e30f;
                #pragma unroll
                for (int j = 0; j < 8; j++)
                    rm = fmaxf(rm, fmaxf(s[j][2 * rr], s[j][2 * rr + 1]));
                rm = fmaxf(rm, __shfl_xor_sync(0xffffffffu, rm, 1));
                rm = fmaxf(rm, __shfl_xor_sync(0xffffffffu, rm, 2));
                const float mn    = fmaxf(m_i[rr], rm);
                const float alpha = exp2_fast(m_i[rr] - mn);
                m_i[rr] = mn;
                float rs = 0.f;
                #pragma unroll
                for (int j = 0; j < 8; j++) {
                    s[j][2 * rr    ] = exp2_fast(s[j][2 * rr    ] - mn);
                    s[j][2 * rr + 1] = exp2_fast(s[j][2 * rr + 1] - mn);
                    rs += s[j][2 * rr] + s[j][2 * rr + 1];
                }
                rs += __shfl_xor_sync(0xffffffffu, rs, 1);
                rs += __shfl_xor_sync(0xffffffffu, rs, 2);
                l_i[rr] = l_i[rr] * alpha + rs;
                #pragma unroll
                for (int j = 0; j < 8; j++) {
                    o[j][2 * rr    ] *= alpha;
                    o[j][2 * rr + 1] *= alpha;
                }
            }

            // ---- write P single (warp-private rows) ----
            #pragma unroll
            for (int j = 0; j < 8; j++) {
                const int p0 = (rw + g) * QSTR + 8 * j + 2 * t;
                const int p1 = p0 + 8 * QSTR;
                *(unsigned*)&Ph[p0] = pk(__float2half_rn(s[j][0]),
                                         __float2half_rn(s[j][1]));
                *(unsigned*)&Ph[p1] = pk(__float2half_rn(s[j][2]),
                                         __float2half_rn(s[j][3]));
            }
            __syncwarp();

            // ---- O += P @ Vh (1-term) ----
            #pragma unroll
            for (int ks = 0; ks < 4; ks++) {
                const int kk = 16 * ks;
                unsigned ph[4];
                ldsm4(ph, Ph + rw * QSTR + kk + aoffQ);
                #pragma unroll
                for (int p = 0; p < 2; p++) {
                    unsigned bh0[4], bh1[4];
                    ldsm4(bh0, Vh + (32 * p     ) * QSTR + kk + boffQ);
                    ldsm4(bh1, Vh + (32 * p + 16) * QSTR + kk + boffQ);
                    const int j0 = 4 * p;
                    mmaF(o[j0 + 0], ph, bh0[0], bh0[1]);
                    mmaF(o[j0 + 1], ph, bh0[2], bh0[3]);
                    mmaF(o[j0 + 2], ph, bh1[0], bh1[1]);
                    mmaF(o[j0 + 3], ph, bh1[2], bh1[3]);
                }
            }
        }
        __syncthreads();
    }

    // ---- normalize + write ctx single [b, s, h*64 + col] ----
    const float inv0 = 1.f / l_i[0];
    const float inv1 = 1.f / l_i[1];
    const int row0 = qt * 128 + rw + g;
    const size_t d0 = ((size_t)b * SEQ + row0    ) * D_MODEL + h * D_HEAD;
    const size_t d1 = ((size_t)b * SEQ + row0 + 8) * D_MODEL + h * D_HEAD;
    #pragma unroll
    for (int j = 0; j < 8; j++) {
        const int cidx = 8 * j + 2 * t;
        *(unsigned*)&g_ch[d0 + cidx] = pk(__float2half_rn(o[j][0] * inv0),
                                          __float2half_rn(o[j][1] * inv0));
        *(unsigned*)&g_ch[d1 + cidx] = pk(__float2half_rn(o[j][2] * inv1),
                                          __float2half_rn(o[j][3] * inv1));
    }
}

// ---------------- launch ----------------------------------------------------
extern "C" void kernel_launch(void* const* d_in, const int* in_sizes, int n_in,
                              void* d_out, int out_size)
{
    (void)in_sizes; (void)n_in; (void)out_size;
    const float* x  = (const float*)d_in[0];
    const float* Qw = (const float*)d_in[1];
    const float* Kw = (const float*)d_in[2];
    const float* Vw = (const float*)d_in[3];
    const float* Ow = (const float*)d_in[4];
    const unsigned char* pm = (const unsigned char*)d_in[5];
    float* out = (float*)d_out;

    cudaFuncSetAttribute(attn_mma, cudaFuncAttributeMaxDynamicSharedMemorySize, ATTN_SMEM);
    cudaFuncSetAttribute(gemm_qkv, cudaFuncAttributeMaxDynamicSharedMemorySize, GEMM_SMEM_SPLIT);
    cudaFuncSetAttribute(gemm_out, cudaFuncAttributeMaxDynamicSharedMemorySize, GEMM_SMEM_SINGLE);

    split_all<<<12288, 256>>>(x, Qw, Kw, Vw, Ow);

    dim3 gq(D_MODEL / 128, MTOT / 128, 3);        // 8 x 64 x 3
    gemm_qkv<<<gq, 256, GEMM_SMEM_SPLIT>>>();

    dim3 ga(SEQ / 128, NUM_HEADS, BATCH);         // 16 x 16 x 4
    attn_mma<<<ga, 256, ATTN_SMEM>>>(pm);

    dim3 go(D_MODEL / 128, MTOT / 128);           // 8 x 64
    gemm_out<<<go, 256, GEMM_SMEM_SINGLE>>>(out);
}

// round 13
// speedup vs baseline: 2.5255x; 1.1669x over previous
#include <cuda_runtime.h>
#include <cuda_fp16.h>
#include <cstdint>

#define D_MODEL   1024
#define NUM_HEADS 16
#define D_HEAD    64
#define BATCH     4
#define SEQ       2048
#define MTOT      (BATCH * SEQ)   // 8192
#define QKV_EL    (BATCH * NUM_HEADS * SEQ * D_HEAD)   // 8388608

// ---------------- scratch (device globals: allocation-guard safe) ----------
__device__ __half g_xh[MTOT * D_MODEL];                // x single fp16
__device__ __half g_wh[4][D_MODEL * D_MODEL];          // weights single fp16
__device__ __half g_qh[QKV_EL];                        // [b,h,s,d] single
__device__ __half g_kh[QKV_EL];                        // [b,h,s,d] single
__device__ __half g_vth[QKV_EL];                       // [b,h,d,s] single
__device__ __half g_ch[MTOT * D_MODEL];                // ctx single

// ---------------- helpers ----------------------------------------------------
__device__ __forceinline__ unsigned pk(__half a, __half b) {
    return (unsigned)__half_as_ushort(a) | ((unsigned)__half_as_ushort(b) << 16);
}
__device__ __forceinline__ void round_store4(float4 v, __half* hp) {
    *(uint2*)hp = make_uint2(pk(__float2half_rn(v.x), __float2half_rn(v.y)),
                             pk(__float2half_rn(v.z), __float2half_rn(v.w)));
}
// fp32-accumulator mma (fp16 inputs)
__device__ __forceinline__ void mmaF(float* c, const unsigned* a, unsigned b0, unsigned b1) {
    asm volatile(
        "mma.sync.aligned.m16n8k16.row.col.f32.f16.f16.f32 "
        "{%0,%1,%2,%3}, {%4,%5,%6,%7}, {%8,%9}, {%0,%1,%2,%3};"
        : "+f"(c[0]), "+f"(c[1]), "+f"(c[2]), "+f"(c[3])
        : "r"(a[0]), "r"(a[1]), "r"(a[2]), "r"(a[3]), "r"(b0), "r"(b1));
}
__device__ __forceinline__ void ldsm4(unsigned r[4], const __half* p) {
    unsigned a = (unsigned)__cvta_generic_to_shared(p);
    asm volatile("ldmatrix.sync.aligned.m8n8.x4.shared.b16 {%0,%1,%2,%3}, [%4];"
                 : "=r"(r[0]), "=r"(r[1]), "=r"(r[2]), "=r"(r[3]) : "r"(a));
}
__device__ __forceinline__ void cp16(__half* s, const __half* g) {
    unsigned sa = (unsigned)__cvta_generic_to_shared(s);
    asm volatile("cp.async.cg.shared.global [%0], [%1], 16;" :: "r"(sa), "l"(g));
}
#define CP_COMMIT() asm volatile("cp.async.commit_group;")
#define CP_WAIT0()  asm volatile("cp.async.wait_group 0;")
#define CP_WAIT1()  asm volatile("cp.async.wait_group 1;")

// fast exp2 on the FMA pipe (MUFU-free)
__device__ __forceinline__ float exp2_fast(float y) {
    y = fmaxf(y, -120.f);
    float z = y + 12582912.f;
    int   e = __float_as_int(z);
    float f = y - (z - 12582912.f);
    float p = 1.f + f * (0.6931471805599453f + f * (0.2402265069591007f +
              f * (0.0555041086648216f + f * (0.0096181291076285f +
              f * 0.0013333558146429f))));
    return __int_as_float(__float_as_int(p) + (e << 23));
}
#define SCALE_LOG2E 0.18033688011112042f   // 0.125 * log2(e)

// ---------------- one-shot fp16 rounding of x + weights ----------------------
__global__ __launch_bounds__(256) void split_all(const float* __restrict__ x,
                                                 const float* __restrict__ Qw,
                                                 const float* __restrict__ Kw,
                                                 const float* __restrict__ Vw,
                                                 const float* __restrict__ Ow)
{
    const int idx = blockIdx.x * 256 + threadIdx.x;        // one float4 each
    if (idx < 2097152) {
        float4 v = ((const float4*)x)[idx];
        round_store4(v, g_xh + (size_t)idx * 4);
    } else {
        const int w = (idx - 2097152) >> 18;
        const size_t off = (size_t)((idx - 2097152) & 262143);
        const float* src = (w == 0) ? Qw : (w == 1) ? Kw : (w == 2) ? Vw : Ow;
        float4 v = ((const float4*)src)[off];
        round_store4(v, g_wh[w] + off * 4);
    }
}

// ---------------- 1-term fp16 GEMM: C = Ah @ Bh^T ----------------------------
// Block tile 128x128, BK=32, 256 threads = 8 warps (4m x 2n), warp tile 32x64.
#define SSTR 40
#define GBUF (128 * SSTR)
#define GSTG (2 * GBUF)               // Ah, Bh
#define GEMM_SMEM (2 * GSTG * 2)      // 40960 bytes

__device__ __forceinline__ void gemm_hf_body(const __half* __restrict__ Agh,
                                             const __half* __restrict__ Bgh,
                                             int m0, int n0,
                                             float (&c)[2][8][4],
                                             __half* sm)
{
    const int tid  = threadIdx.x;
    const int lane = tid & 31;
    const int warp = tid >> 5;
    const int wm   = (warp >> 1) * 32;
    const int wn   = (warp & 1) * 64;
    const int lrow = tid >> 1;
    const int lcol = (tid & 1) * 16;
    const int so   = lrow * SSTR + lcol;

    const int aoff = ((lane & 7) + ((lane >> 3) & 1) * 8) * SSTR + (lane >> 4) * 8;
    const int boff = ((lane & 7) + (lane >> 4) * 8) * SSTR + ((lane >> 3) & 1) * 8;

    const size_t arow = (size_t)(m0 + lrow) * D_MODEL + lcol;
    const size_t brow = (size_t)(n0 + lrow) * D_MODEL + lcol;

    {   // prologue: stage 0 <- k-tile 0
        __half* st = sm;
        cp16(st + so,        Agh + arow); cp16(st + so + 8,        Agh + arow + 8);
        cp16(st + GBUF + so, Bgh + brow); cp16(st + GBUF + so + 8, Bgh + brow + 8);
        CP_COMMIT();
        CP_WAIT0();
    }
    __syncthreads();

    for (int kt = 0; kt < 32; kt++) {
        if (kt + 1 < 32) {
            __half* nx = sm + ((kt + 1) & 1) * GSTG;
            const int k0 = (kt + 1) * 32;
            cp16(nx + so,        Agh + arow + k0); cp16(nx + so + 8,        Agh + arow + k0 + 8);
            cp16(nx + GBUF + so, Bgh + brow + k0); cp16(nx + GBUF + so + 8, Bgh + brow + k0 + 8);
            CP_COMMIT();
        }

        const __half* Ah = sm + (kt & 1) * GSTG;
        const __half* Bh = Ah + GBUF;

        #pragma unroll
        for (int ks = 0; ks < 2; ks++) {
            const int kk = ks * 16;
            unsigned ahi[2][4];
            ldsm4(ahi[0], Ah + (wm     ) * SSTR + kk + aoff);
            ldsm4(ahi[1], Ah + (wm + 16) * SSTR + kk + aoff);
            #pragma unroll
            for (int p = 0; p < 2; p++) {
                unsigned bh0[4], bh1[4];
                ldsm4(bh0, Bh + (wn + 32 * p     ) * SSTR + kk + boff);
                ldsm4(bh1, Bh + (wn + 32 * p + 16) * SSTR + kk + boff);
                const int j0 = 4 * p;
                mmaF(c[0][j0 + 0], ahi[0], bh0[0], bh0[1]);
                mmaF(c[1][j0 + 0], ahi[1], bh0[0], bh0[1]);
                mmaF(c[0][j0 + 1], ahi[0], bh0[2], bh0[3]);
                mmaF(c[1][j0 + 1], ahi[1], bh0[2], bh0[3]);
                mmaF(c[0][j0 + 2], ahi[0], bh1[0], bh1[1]);
                mmaF(c[1][j0 + 2], ahi[1], bh1[0], bh1[1]);
                mmaF(c[0][j0 + 3], ahi[0], bh1[2], bh1[3]);
                mmaF(c[1][j0 + 3], ahi[1], bh1[2], bh1[3]);
            }
        }
        CP_WAIT0();
        __syncthreads();
    }
}

// Fused QKV projection; blockIdx.z selects weight. All 1-term.
// Q (z=0): single [b,h,s,d]; K (z=1): single [b,h,s,d];
// V (z=2): single [b,h,d,s], coalesced via smem transpose.
__global__ __launch_bounds__(256, 2) void gemm_qkv()
{
    extern __shared__ __half smg[];
    float c[2][8][4];
    #pragma unroll
    for (int i = 0; i < 2; i++)
        #pragma unroll
        for (int j = 0; j < 8; j++)
            #pragma unroll
            for (int q = 0; q < 4; q++) c[i][j][q] = 0.f;

    const int m0 = blockIdx.y * 128;
    const int n0 = blockIdx.x * 128;
    const int z  = blockIdx.z;

    gemm_hf_body(g_xh, g_wh[z], m0, n0, c, smg);

    const int tid  = threadIdx.x;
    const int lane = tid & 31;
    const int g = lane >> 2, t = lane & 3;
    const int warp = tid >> 5;
    const int wm = (warp >> 1) * 32, wn = (warp & 1) * 64;

    if (z == 2) {
        // ---- smem transpose: vs[n - n0][m - m0], stride 136 (16B-aligned rows)
        #define VS 136
        __half* vs = smg;
        __syncthreads();   // mainloop done with smem everywhere before reuse
        #pragma unroll
        for (int i = 0; i < 2; i++) {
            #pragma unroll
            for (int j = 0; j < 8; j++) {
                const int nn = wn + 8 * j + 2 * t;
                const int mm = wm + 16 * i + g;
                vs[(nn    ) * VS + mm    ] = __float2half_rn(c[i][j][0]);
                vs[(nn + 1) * VS + mm    ] = __float2half_rn(c[i][j][1]);
                vs[(nn    ) * VS + mm + 8] = __float2half_rn(c[i][j][2]);
                vs[(nn + 1) * VS + mm + 8] = __float2half_rn(c[i][j][3]);
            }
        }
        __syncthreads();
        // ---- coalesced store: row = n (head*64+d), cols = 128 contiguous s
        const int r    = tid >> 1;             // 0..127
        const int cseg = (tid & 1) * 64;       // 0 / 64
        const int n = n0 + r;
        const int h = n >> 6, d = n & 63;
        const int b = m0 >> 11, s0 = m0 & 2047;
        __half* dst = g_vth + ((size_t)(b * NUM_HEADS + h) * D_HEAD + d) * SEQ + s0 + cseg;
        const __half* src = vs + r * VS + cseg;
        #pragma unroll
        for (int u = 0; u < 8; u++)
            *(uint4*)&dst[8 * u] = *(const uint4*)&src[8 * u];
        #undef VS
    } else {
        __half* dst = (z == 0) ? g_qh : g_kh;
        #pragma unroll
        for (int i = 0; i < 2; i++) {
            #pragma unroll
            for (int j = 0; j < 8; j++) {
                const int n = n0 + wn + 8 * j + 2 * t;
                const int h = n >> 6, d = n & 63;
                const int r0 = m0 + wm + 16 * i + g;
                const int r1 = r0 + 8;
                const int b0 = r0 >> 11, s0 = r0 & 2047;
                const int b1 = r1 >> 11, s1 = r1 & 2047;
                const size_t i0 = ((size_t)(b0 * NUM_HEADS + h) * SEQ + s0) * D_HEAD + d;
                const size_t i1 = ((size_t)(b1 * NUM_HEADS + h) * SEQ + s1) * D_HEAD + d;
                *(unsigned*)&dst[i0] = pk(__float2half_rn(c[i][j][0]),
                                          __float2half_rn(c[i][j][1]));
                *(unsigned*)&dst[i1] = pk(__float2half_rn(c[i][j][2]),
                                          __float2half_rn(c[i][j][3]));
            }
        }
    }
}

// Output projection: out = ctx @ Ow^T, fp32 out. 1-term GEMM.
__global__ __launch_bounds__(256, 2) void gemm_out(float* __restrict__ out)
{
    extern __shared__ __half smg[];
    float c[2][8][4];
    #pragma unroll
    for (int i = 0; i < 2; i++)
        #pragma unroll
        for (int j = 0; j < 8; j++)
            #pragma unroll
            for (int q = 0; q < 4; q++) c[i][j][q] = 0.f;

    const int m0 = blockIdx.y * 128;
    const int n0 = blockIdx.x * 128;

    gemm_hf_body(g_ch, g_wh[3], m0, n0, c, smg);

    const int lane = threadIdx.x & 31;
    const int g = lane >> 2, t = lane & 3;
    const int warp = threadIdx.x >> 5;
    const int wm = (warp >> 1) * 32, wn = (warp & 1) * 64;

    #pragma unroll
    for (int i = 0; i < 2; i++) {
        #pragma unroll
        for (int j = 0; j < 8; j++) {
            const int n  = n0 + wn + 8 * j + 2 * t;
            const int r0 = m0 + wm + 16 * i + g;
            *(float2*)&out[(size_t)r0 * D_MODEL + n] = make_float2(c[i][j][0], c[i][j][1]);
            *(float2*)&out[(size_t)(r0 + 8) * D_MODEL + n] = make_float2(c[i][j][2], c[i][j][3]);
        }
    }
}

// ---------------- Flash attention: all fp16 single, 1-term mma ---------------
// Block = (b, h, 128-q-tile). 256 threads = 8 warps. KV tiles of 64.
#define QSTR 72
#define TILEC (64 * QSTR)
#define ATTN_SMEM (6 * TILEC * 2)         // 55296 bytes: 2 KV stages + Ph

__global__ __launch_bounds__(256, 2) void attn_mma(const unsigned char* __restrict__ pm)
{
    extern __shared__ __half smb[];
    __half* stg0 = smb;                   // {Kh, Vth} stage 0
    __half* stg1 = smb + 2 * TILEC;       // stage 1
    __half* Ph   = smb + 4 * TILEC;       // P single (128 rows)

    const int qt = gridDim.x - 1 - blockIdx.x;
    const int h  = blockIdx.y;
    const int b  = blockIdx.z;
    const int tid  = threadIdx.x;
    const int lane = tid & 31;
    const int warp = tid >> 5;
    const int g = lane >> 2, t = lane & 3;
    const size_t base = (size_t)(b * NUM_HEADS + h) * SEQ;

    const int rw = warp * 16;
    const int Rg = qt * 128 + rw;
    const int kt_max = 2 * qt + 1;

    const int aoffQ = ((lane & 7) + ((lane >> 3) & 1) * 8) * QSTR + (lane >> 4) * 8;
    const int boffQ = ((lane & 7) + (lane >> 4) * 8) * QSTR + ((lane >> 3) & 1) * 8;

    const int krow = tid >> 2;
    const int kcs  = (tid & 3) * 16;
    const int kso  = krow * QSTR + kcs;
    const size_t vbase = ((size_t)(b * NUM_HEADS + h) * D_HEAD + krow) * SEQ + kcs;
    const size_t kbase = (base + krow) * D_HEAD + kcs;

    // ---- stage Q single into smb[0..2T), move to regs ----
    {
        const int row = tid >> 1, cs = (tid & 1) * 32;
        const size_t ga = (base + (size_t)qt * 128 + row) * D_HEAD + cs;
        const int so = row * QSTR + cs;
        #pragma unroll
        for (int u = 0; u < 4; u++)
            cp16(&smb[so + 8 * u], &g_qh[ga + 8 * u]);
        CP_COMMIT();
        CP_WAIT0();
    }
    __syncthreads();

    unsigned qh[4][4];
    #pragma unroll
    for (int ks = 0; ks < 4; ks++)
        ldsm4(qh[ks], smb + rw * QSTR + 16 * ks + aoffQ);
    __syncthreads();                      // smem free for KV stages

    // ---- prologue: KV(0) into stg0 ----
    {
        cp16(&stg0[kso],         &g_kh[kbase]);  cp16(&stg0[kso + 8],         &g_kh[kbase + 8]);
        cp16(&stg0[TILEC + kso], &g_vth[vbase]); cp16(&stg0[TILEC + kso + 8], &g_vth[vbase + 8]);
        CP_COMMIT();
    }

    float o[8][4];
    float m_i[2] = {-1e30f, -1e30f};
    float l_i[2] = {0.f, 0.f};
    #pragma unroll
    for (int j = 0; j < 8; j++)
        #pragma unroll
        for (int q = 0; q < 4; q++) o[j][q] = 0.f;

    for (int kt = 0; kt <= kt_max; kt++) {
        if (kt < kt_max) {
            __half* nx = ((kt + 1) & 1) ? stg1 : stg0;
            const size_t gk = kbase + (size_t)(kt + 1) * 64 * D_HEAD;
            const size_t gv = vbase + (size_t)(kt + 1) * 64;
            cp16(&nx[kso],         &g_kh[gk]);  cp16(&nx[kso + 8],         &g_kh[gk + 8]);
            cp16(&nx[TILEC + kso], &g_vth[gv]); cp16(&nx[TILEC + kso + 8], &g_vth[gv + 8]);
            CP_COMMIT();
            CP_WAIT1();                    // KV(kt) complete
        } else {
            CP_WAIT0();
        }
        __syncthreads();

        const int C0 = kt * 64;
        if (C0 <= Rg + 15) {
            const __half* Kh = (kt & 1) ? stg1 : stg0;
            const __half* Vh = Kh + TILEC;

            float s[8][4];
            #pragma unroll
            for (int j = 0; j < 8; j++)
                #pragma unroll
                for (int q = 0; q < 4; q++) s[j][q] = 0.f;

            // ---- S = Q @ Kh^T (1-term) ----
            #pragma unroll
            for (int ks = 0; ks < 4; ks++) {
                const int kk = 16 * ks;
                #pragma unroll
                for (int p = 0; p < 2; p++) {
                    unsigned bh0[4], bh1[4];
                    ldsm4(bh0, Kh + (32 * p     ) * QSTR + kk + boffQ);
                    ldsm4(bh1, Kh + (32 * p + 16) * QSTR + kk + boffQ);
                    const int j0 = 4 * p;
                    mmaF(s[j0 + 0], qh[ks], bh0[0], bh0[1]);
                    mmaF(s[j0 + 1], qh[ks], bh0[2], bh0[3]);
                    mmaF(s[j0 + 2], qh[ks], bh1[0], bh1[1]);
                    mmaF(s[j0 + 3], qh[ks], bh1[2], bh1[3]);
                }
            }

            // ---- scale (log2 domain) + causal + padding masks ----
            const unsigned char* pmb = pm + (size_t)b * SEQ + C0;
            const int r0 = Rg + g, r1 = r0 + 8;
            #pragma unroll
            for (int j = 0; j < 8; j++) {
                const int c0 = C0 + 8 * j + 2 * t, c1 = c0 + 1;
                const bool p0 = pmb[8 * j + 2 * t] != 0;
                const bool p1 = pmb[8 * j + 2 * t + 1] != 0;
                float v;
                v = s[j][0] * SCALE_LOG2E; if (c0 > r0 || p0) v = -1e30f; s[j][0] = v;
                v = s[j][1] * SCALE_LOG2E; if (c1 > r0 || p1) v = -1e30f; s[j][1] = v;
                v = s[j][2] * SCALE_LOG2E; if (c0 > r1 || p0) v = -1e30f; s[j][2] = v;
                v = s[j][3] * SCALE_LOG2E; if (c1 > r1 || p1) v = -1e30f; s[j][3] = v;
            }

            // ---- online softmax, base-2, FMA-pipe exp ----
            #pragma unroll
            for (int rr = 0; rr < 2; rr++) {
                float rm = -1e30f;
                #pragma unroll
                for (int j = 0; j < 8; j++)
                    rm = fmaxf(rm, fmaxf(s[j][2 * rr], s[j][2 * rr + 1]));
                rm = fmaxf(rm, __shfl_xor_sync(0xffffffffu, rm, 1));
                rm = fmaxf(rm, __shfl_xor_sync(0xffffffffu, rm, 2));
                const float mn    = fmaxf(m_i[rr], rm);
                const float alpha = exp2_fast(m_i[rr] - mn);
                m_i[rr] = mn;
                float rs = 0.f;
                #pragma unroll
                for (int j = 0; j < 8; j++) {
                    s[j][2 * rr    ] = exp2_fast(s[j][2 * rr    ] - mn);
                    s[j][2 * rr + 1] = exp2_fast(s[j][2 * rr + 1] - mn);
                    rs += s[j][2 * rr] + s[j][2 * rr + 1];
                }
                rs += __shfl_xor_sync(0xffffffffu, rs, 1);
                rs += __shfl_xor_sync(0xffffffffu, rs, 2);
                l_i[rr] = l_i[rr] * alpha + rs;
                #pragma unroll
                for (int j = 0; j < 8; j++) {
                    o[j][2 * rr    ] *= alpha;
                    o[j][2 * rr + 1] *= alpha;
                }
            }

            // ---- write P single (warp-private rows) ----
            #pragma unroll
            for (int j = 0; j < 8; j++) {
                const int p0 = (rw + g) * QSTR + 8 * j + 2 * t;
                const int p1 = p0 + 8 * QSTR;
                *(unsigned*)&Ph[p0] = pk(__float2half_rn(s[j][0]),
                                         __float2half_rn(s[j][1]));
                *(unsigned*)&Ph[p1] = pk(__float2half_rn(s[j][2]),
                                         __float2half_rn(s[j][3]));
            }
            __syncwarp();

            // ---- O += P @ Vh (1-term) ----
            #pragma unroll
            for (int ks = 0; ks < 4; ks++) {
                const int kk = 16 * ks;
                unsigned ph[4];
                ldsm4(ph, Ph + rw * QSTR + kk + aoffQ);
                #pragma unroll
                for (int p = 0; p < 2; p++) {
                    unsigned bh0[4], bh1[4];
                    ldsm4(bh0, Vh + (32 * p     ) * QSTR + kk + boffQ);
                    ldsm4(bh1, Vh + (32 * p + 16) * QSTR + kk + boffQ);
                    const int j0 = 4 * p;
                    mmaF(o[j0 + 0], ph, bh0[0], bh0[1]);
                    mmaF(o[j0 + 1], ph, bh0[2], bh0[3]);
                    mmaF(o[j0 + 2], ph, bh1[0], bh1[1]);
                    mmaF(o[j0 + 3], ph, bh1[2], bh1[3]);
                }
            }
        }
        __syncthreads();
    }

    // ---- normalize + write ctx single [b, s, h*64 + col] ----
    const float inv0 = 1.f / l_i[0];
    const float inv1 = 1.f / l_i[1];
    const int row0 = qt * 128 + rw + g;
    const size_t d0 = ((size_t)b * SEQ + row0    ) * D_MODEL + h * D_HEAD;
    const size_t d1 = ((size_t)b * SEQ + row0 + 8) * D_MODEL + h * D_HEAD;
    #pragma unroll
    for (int j = 0; j < 8; j++) {
        const int cidx = 8 * j + 2 * t;
        *(unsigned*)&g_ch[d0 + cidx] = pk(__float2half_rn(o[j][0] * inv0),
                                          __float2half_rn(o[j][1] * inv0));
        *(unsigned*)&g_ch[d1 + cidx] = pk(__float2half_rn(o[j][2] * inv1),
                                          __float2half_rn(o[j][3] * inv1));
    }
}

// ---------------- launch ----------------------------------------------------
extern "C" void kernel_launch(void* const* d_in, const int* in_sizes, int n_in,
                              void* d_out, int out_size)
{
    (void)in_sizes; (void)n_in; (void)out_size;
    const float* x  = (const float*)d_in[0];
    const float* Qw = (const float*)d_in[1];
    const float* Kw = (const float*)d_in[2];
    const float* Vw = (const float*)d_in[3];
    const float* Ow = (const float*)d_in[4];
    const unsigned char* pm = (const unsigned char*)d_in[5];
    float* out = (float*)d_out;

    cudaFuncSetAttribute(attn_mma, cudaFuncAttributeMaxDynamicSharedMemorySize, ATTN_SMEM);
    cudaFuncSetAttribute(gemm_qkv, cudaFuncAttributeMaxDynamicSharedMemorySize, GEMM_SMEM);
    cudaFuncSetAttribute(gemm_out, cudaFuncAttributeMaxDynamicSharedMemorySize, GEMM_SMEM);

    split_all<<<12288, 256>>>(x, Qw, Kw, Vw, Ow);

    dim3 gq(D_MODEL / 128, MTOT / 128, 3);        // 8 x 64 x 3
    gemm_qkv<<<gq, 256, GEMM_SMEM>>>();

    dim3 ga(SEQ / 128, NUM_HEADS, BATCH);         // 16 x 16 x 4
    attn_mma<<<ga, 256, ATTN_SMEM>>>(pm);

    dim3 go(D_MODEL / 128, MTOT / 128);           // 8 x 64
    gemm_out<<<go, 256, GEMM_SMEM>>>(out);
}

// round 14
// speedup vs baseline: 2.7619x; 1.0936x over previous
#include <cuda_runtime.h>
#include <cuda_fp16.h>
#include <cstdint>

#define D_MODEL   1024
#define NUM_HEADS 16
#define D_HEAD    64
#define BATCH     4
#define SEQ       2048
#define MTOT      (BATCH * SEQ)   // 8192
#define QKV_EL    (BATCH * NUM_HEADS * SEQ * D_HEAD)   // 8388608

// ---------------- scratch (device globals: allocation-guard safe) ----------
__device__ __half g_xh[MTOT * D_MODEL];                // x single fp16
__device__ __half g_wh[4][D_MODEL * D_MODEL];          // weights single fp16
__device__ __half g_qh[QKV_EL];                        // [b,h,s,d] single
__device__ __half g_kh[QKV_EL];                        // [b,h,s,d] single
__device__ __half g_vth[QKV_EL];                       // [b,h,d,s] single
__device__ __half g_ch[MTOT * D_MODEL];                // ctx single

// ---------------- helpers ----------------------------------------------------
__device__ __forceinline__ unsigned pk(__half a, __half b) {
    return (unsigned)__half_as_ushort(a) | ((unsigned)__half_as_ushort(b) << 16);
}
__device__ __forceinline__ void round_store4(float4 v, __half* hp) {
    *(uint2*)hp = make_uint2(pk(__float2half_rn(v.x), __float2half_rn(v.y)),
                             pk(__float2half_rn(v.z), __float2half_rn(v.w)));
}
// fp32-accumulator mma (fp16 inputs)
__device__ __forceinline__ void mmaF(float* c, const unsigned* a, unsigned b0, unsigned b1) {
    asm volatile(
        "mma.sync.aligned.m16n8k16.row.col.f32.f16.f16.f32 "
        "{%0,%1,%2,%3}, {%4,%5,%6,%7}, {%8,%9}, {%0,%1,%2,%3};"
        : "+f"(c[0]), "+f"(c[1]), "+f"(c[2]), "+f"(c[3])
        : "r"(a[0]), "r"(a[1]), "r"(a[2]), "r"(a[3]), "r"(b0), "r"(b1));
}
__device__ __forceinline__ void ldsm4(unsigned r[4], const __half* p) {
    unsigned a = (unsigned)__cvta_generic_to_shared(p);
    asm volatile("ldmatrix.sync.aligned.m8n8.x4.shared.b16 {%0,%1,%2,%3}, [%4];"
                 : "=r"(r[0]), "=r"(r[1]), "=r"(r[2]), "=r"(r[3]) : "r"(a));
}
__device__ __forceinline__ void cp16(__half* s, const __half* g) {
    unsigned sa = (unsigned)__cvta_generic_to_shared(s);
    asm volatile("cp.async.cg.shared.global [%0], [%1], 16;" :: "r"(sa), "l"(g));
}
#define CP_COMMIT() asm volatile("cp.async.commit_group;")
#define CP_WAIT0()  asm volatile("cp.async.wait_group 0;")
#define CP_WAIT1()  asm volatile("cp.async.wait_group 1;")

// fast exp2 on the FMA pipe (MUFU-free)
__device__ __forceinline__ float exp2_fast(float y) {
    y = fmaxf(y, -120.f);
    float z = y + 12582912.f;
    int   e = __float_as_int(z);
    float f = y - (z - 12582912.f);
    float p = 1.f + f * (0.6931471805599453f + f * (0.2402265069591007f +
              f * (0.0555041086648216f + f * (0.0096181291076285f +
              f * 0.0013333558146429f))));
    return __int_as_float(__float_as_int(p) + (e << 23));
}
#define SCALE_LOG2E 0.18033688011112042f   // 0.125 * log2(e)

// ---------------- one-shot fp16 rounding of x + weights ----------------------
__global__ __launch_bounds__(256) void split_all(const float* __restrict__ x,
                                                 const float* __restrict__ Qw,
                                                 const float* __restrict__ Kw,
                                                 const float* __restrict__ Vw,
                                                 const float* __restrict__ Ow)
{
    const int idx = blockIdx.x * 256 + threadIdx.x;        // one float4 each
    if (idx < 2097152) {
        float4 v = ((const float4*)x)[idx];
        round_store4(v, g_xh + (size_t)idx * 4);
    } else {
        const int w = (idx - 2097152) >> 18;
        const size_t off = (size_t)((idx - 2097152) & 262143);
        const float* src = (w == 0) ? Qw : (w == 1) ? Kw : (w == 2) ? Vw : Ow;
        float4 v = ((const float4*)src)[off];
        round_store4(v, g_wh[w] + off * 4);
    }
}

// ---------------- 1-term fp16 GEMM: C = Ah @ Bh^T ----------------------------
// Block tile 128x128, BK=32, 128 threads = 4 warps (2m x 2n), warp tile 64x64.
// Each B-ldsm4 now feeds 8 mma (4 m-blocks x 2 n-cols): half the smem reads/FLOP.
#define SSTR 40
#define GBUF (128 * SSTR)
#define GSTG (2 * GBUF)               // Ah, Bh
#define GEMM_SMEM (2 * GSTG * 2)      // 40960 bytes

__device__ __forceinline__ void gemm_hf_body(const __half* __restrict__ Agh,
                                             const __half* __restrict__ Bgh,
                                             int m0, int n0,
                                             float (&c)[4][8][4],
                                             __half* sm)
{
    const int tid  = threadIdx.x;
    const int lane = tid & 31;
    const int warp = tid >> 5;
    const int wm   = (warp >> 1) * 64;
    const int wn   = (warp & 1) * 64;

    const int aoff = ((lane & 7) + ((lane >> 3) & 1) * 8) * SSTR + (lane >> 4) * 8;
    const int boff = ((lane & 7) + (lane >> 4) * 8) * SSTR + ((lane >> 3) & 1) * 8;

    // loader: 128x32 tile = 512 x 16B chunks; 4 per thread per tile, coalesced
    int rowL[4], colL[4];
    #pragma unroll
    for (int u = 0; u < 4; u++) {
        const int idx = tid + 128 * u;
        rowL[u] = idx >> 2;
        colL[u] = (idx & 3) * 8;
    }

    {   // prologue: stage 0 <- k-tile 0
        __half* st = sm;
        #pragma unroll
        for (int u = 0; u < 4; u++) {
            const int so = rowL[u] * SSTR + colL[u];
            cp16(st + so,        Agh + (size_t)(m0 + rowL[u]) * D_MODEL + colL[u]);
            cp16(st + GBUF + so, Bgh + (size_t)(n0 + rowL[u]) * D_MODEL + colL[u]);
        }
        CP_COMMIT();
        CP_WAIT0();
    }
    __syncthreads();

    for (int kt = 0; kt < 32; kt++) {
        if (kt + 1 < 32) {
            __half* nx = sm + ((kt + 1) & 1) * GSTG;
            const int k0 = (kt + 1) * 32;
            #pragma unroll
            for (int u = 0; u < 4; u++) {
                const int so = rowL[u] * SSTR + colL[u];
                cp16(nx + so,        Agh + (size_t)(m0 + rowL[u]) * D_MODEL + k0 + colL[u]);
                cp16(nx + GBUF + so, Bgh + (size_t)(n0 + rowL[u]) * D_MODEL + k0 + colL[u]);
            }
            CP_COMMIT();
        }

        const __half* Ah = sm + (kt & 1) * GSTG;
        const __half* Bh = Ah + GBUF;

        #pragma unroll
        for (int ks = 0; ks < 2; ks++) {
            const int kk = ks * 16;
            unsigned a[4][4];
            #pragma unroll
            for (int i = 0; i < 4; i++)
                ldsm4(a[i], Ah + (wm + 16 * i) * SSTR + kk + aoff);
            #pragma unroll
            for (int p = 0; p < 4; p++) {
                unsigned bh[4];
                ldsm4(bh, Bh + (wn + 16 * p) * SSTR + kk + boff);
                const int j0 = 2 * p, j1 = j0 + 1;
                #pragma unroll
                for (int i = 0; i < 4; i++) {
                    mmaF(c[i][j0], a[i], bh[0], bh[1]);
                    mmaF(c[i][j1], a[i], bh[2], bh[3]);
                }
            }
        }
        CP_WAIT0();
        __syncthreads();
    }
}

// Fused QKV projection; blockIdx.z selects weight. All 1-term.
// Q (z=0): single [b,h,s,d]; K (z=1): single [b,h,s,d];
// V (z=2): single [b,h,d,s], coalesced via smem transpose.
__global__ __launch_bounds__(128, 2) void gemm_qkv()
{
    extern __shared__ __half smg[];
    float c[4][8][4];
    #pragma unroll
    for (int i = 0; i < 4; i++)
        #pragma unroll
        for (int j = 0; j < 8; j++)
            #pragma unroll
            for (int q = 0; q < 4; q++) c[i][j][q] = 0.f;

    const int m0 = blockIdx.y * 128;
    const int n0 = blockIdx.x * 128;
    const int z  = blockIdx.z;

    gemm_hf_body(g_xh, g_wh[z], m0, n0, c, smg);

    const int tid  = threadIdx.x;
    const int lane = tid & 31;
    const int g = lane >> 2, t = lane & 3;
    const int warp = tid >> 5;
    const int wm = (warp >> 1) * 64, wn = (warp & 1) * 64;

    if (z == 2) {
        // ---- smem transpose: vs[n - n0][m - m0], stride 136 (16B-aligned rows)
        #define VS 136
        __half* vs = smg;
        __syncthreads();   // mainloop done with smem everywhere before reuse
        #pragma unroll
        for (int i = 0; i < 4; i++) {
            #pragma unroll
            for (int j = 0; j < 8; j++) {
                const int nn = wn + 8 * j + 2 * t;
                const int mm = wm + 16 * i + g;
                vs[(nn    ) * VS + mm    ] = __float2half_rn(c[i][j][0]);
                vs[(nn + 1) * VS + mm    ] = __float2half_rn(c[i][j][1]);
                vs[(nn    ) * VS + mm + 8] = __float2half_rn(c[i][j][2]);
                vs[(nn + 1) * VS + mm + 8] = __float2half_rn(c[i][j][3]);
            }
        }
        __syncthreads();
        // ---- coalesced store: row = n (head*64+d), 128 contiguous s cols
        const int r = tid;                     // 0..127
        const int n = n0 + r;
        const int h = n >> 6, d = n & 63;
        const int b = m0 >> 11, s0 = m0 & 2047;
        __half* dst = g_vth + ((size_t)(b * NUM_HEADS + h) * D_HEAD + d) * SEQ + s0;
        const __half* src = vs + r * VS;
        #pragma unroll
        for (int u = 0; u < 16; u++)
            *(uint4*)&dst[8 * u] = *(const uint4*)&src[8 * u];
        #undef VS
    } else {
        __half* dst = (z == 0) ? g_qh : g_kh;
        #pragma unroll
        for (int i = 0; i < 4; i++) {
            #pragma unroll
            for (int j = 0; j < 8; j++) {
                const int n = n0 + wn + 8 * j + 2 * t;
                const int h = n >> 6, d = n & 63;
                const int r0 = m0 + wm + 16 * i + g;
                const int r1 = r0 + 8;
                const int b0 = r0 >> 11, s0 = r0 & 2047;
                const int b1 = r1 >> 11, s1 = r1 & 2047;
                const size_t i0 = ((size_t)(b0 * NUM_HEADS + h) * SEQ + s0) * D_HEAD + d;
                const size_t i1 = ((size_t)(b1 * NUM_HEADS + h) * SEQ + s1) * D_HEAD + d;
                *(unsigned*)&dst[i0] = pk(__float2half_rn(c[i][j][0]),
                                          __float2half_rn(c[i][j][1]));
                *(unsigned*)&dst[i1] = pk(__float2half_rn(c[i][j][2]),
                                          __float2half_rn(c[i][j][3]));
            }
        }
    }
}

// Output projection: out = ctx @ Ow^T, fp32 out. 1-term GEMM.
__global__ __launch_bounds__(128, 2) void gemm_out(float* __restrict__ out)
{
    extern __shared__ __half smg[];
    float c[4][8][4];
    #pragma unroll
    for (int i = 0; i < 4; i++)
        #pragma unroll
        for (int j = 0; j < 8; j++)
            #pragma unroll
            for (int q = 0; q < 4; q++) c[i][j][q] = 0.f;

    const int m0 = blockIdx.y * 128;
    const int n0 = blockIdx.x * 128;

    gemm_hf_body(g_ch, g_wh[3], m0, n0, c, smg);

    const int lane = threadIdx.x & 31;
    const int g = lane >> 2, t = lane & 3;
    const int warp = threadIdx.x >> 5;
    const int wm = (warp >> 1) * 64, wn = (warp & 1) * 64;

    #pragma unroll
    for (int i = 0; i < 4; i++) {
        #pragma unroll
        for (int j = 0; j < 8; j++) {
            const int n  = n0 + wn + 8 * j + 2 * t;
            const int r0 = m0 + wm + 16 * i + g;
            *(float2*)&out[(size_t)r0 * D_MODEL + n] = make_float2(c[i][j][0], c[i][j][1]);
            *(float2*)&out[(size_t)(r0 + 8) * D_MODEL + n] = make_float2(c[i][j][2], c[i][j][3]);
        }
    }
}

// ---------------- Flash attention: all fp16 single, 1-term mma ---------------
// Block = (b, h, 128-q-tile). 256 threads = 8 warps. KV tiles of 64.
#define QSTR 72
#define TILEC (64 * QSTR)
#define ATTN_SMEM (6 * TILEC * 2)         // 55296 bytes: 2 KV stages + Ph

__global__ __launch_bounds__(256, 2) void attn_mma(const unsigned char* __restrict__ pm)
{
    extern __shared__ __half smb[];
    __half* stg0 = smb;                   // {Kh, Vth} stage 0
    __half* stg1 = smb + 2 * TILEC;       // stage 1
    __half* Ph   = smb + 4 * TILEC;       // P single (128 rows)

    const int qt = gridDim.x - 1 - blockIdx.x;
    const int h  = blockIdx.y;
    const int b  = blockIdx.z;
    const int tid  = threadIdx.x;
    const int lane = tid & 31;
    const int warp = tid >> 5;
    const int g = lane >> 2, t = lane & 3;
    const size_t base = (size_t)(b * NUM_HEADS + h) * SEQ;

    const int rw = warp * 16;
    const int Rg = qt * 128 + rw;
    const int kt_max = 2 * qt + 1;

    const int aoffQ = ((lane & 7) + ((lane >> 3) & 1) * 8) * QSTR + (lane >> 4) * 8;
    const int boffQ = ((lane & 7) + (lane >> 4) * 8) * QSTR + ((lane >> 3) & 1) * 8;

    const int krow = tid >> 2;
    const int kcs  = (tid & 3) * 16;
    const int kso  = krow * QSTR + kcs;
    const size_t vbase = ((size_t)(b * NUM_HEADS + h) * D_HEAD + krow) * SEQ + kcs;
    const size_t kbase = (base + krow) * D_HEAD + kcs;

    // ---- stage Q single into smb[0..2T), move to regs ----
    {
        const int row = tid >> 1, cs = (tid & 1) * 32;
        const size_t ga = (base + (size_t)qt * 128 + row) * D_HEAD + cs;
        const int so = row * QSTR + cs;
        #pragma unroll
        for (int u = 0; u < 4; u++)
            cp16(&smb[so + 8 * u], &g_qh[ga + 8 * u]);
        CP_COMMIT();
        CP_WAIT0();
    }
    __syncthreads();

    unsigned qh[4][4];
    #pragma unroll
    for (int ks = 0; ks < 4; ks++)
        ldsm4(qh[ks], smb + rw * QSTR + 16 * ks + aoffQ);
    __syncthreads();                      // smem free for KV stages

    // ---- prologue: KV(0) into stg0 ----
    {
        cp16(&stg0[kso],         &g_kh[kbase]);  cp16(&stg0[kso + 8],         &g_kh[kbase + 8]);
        cp16(&stg0[TILEC + kso], &g_vth[vbase]); cp16(&stg0[TILEC + kso + 8], &g_vth[vbase + 8]);
        CP_COMMIT();
    }

    float o[8][4];
    float m_i[2] = {-1e30f, -1e30f};
    float l_i[2] = {0.f, 0.f};
    #pragma unroll
    for (int j = 0; j < 8; j++)
        #pragma unroll
        for (int q = 0; q < 4; q++) o[j][q] = 0.f;

    for (int kt = 0; kt <= kt_max; kt++) {
        if (kt < kt_max) {
            __half* nx = ((kt + 1) & 1) ? stg1 : stg0;
            const size_t gk = kbase + (size_t)(kt + 1) * 64 * D_HEAD;
            const size_t gv = vbase + (size_t)(kt + 1) * 64;
            cp16(&nx[kso],         &g_kh[gk]);  cp16(&nx[kso + 8],         &g_kh[gk + 8]);
            cp16(&nx[TILEC + kso], &g_vth[gv]); cp16(&nx[TILEC + kso + 8], &g_vth[gv + 8]);
            CP_COMMIT();
            CP_WAIT1();                    // KV(kt) complete
        } else {
            CP_WAIT0();
        }
        __syncthreads();

        const int C0 = kt * 64;
        if (C0 <= Rg + 15) {
            const __half* Kh = (kt & 1) ? stg1 : stg0;
            const __half* Vh = Kh + TILEC;

            float s[8][4];
            #pragma unroll
            for (int j = 0; j < 8; j++)
                #pragma unroll
                for (int q = 0; q < 4; q++) s[j][q] = 0.f;

            // ---- S = Q @ Kh^T (1-term) ----
            #pragma unroll
            for (int ks = 0; ks < 4; ks++) {
                const int kk = 16 * ks;
                #pragma unroll
                for (int p = 0; p < 2; p++) {
                    unsigned bh0[4], bh1[4];
                    ldsm4(bh0, Kh + (32 * p     ) * QSTR + kk + boffQ);
                    ldsm4(bh1, Kh + (32 * p + 16) * QSTR + kk + boffQ);
                    const int j0 = 4 * p;
                    mmaF(s[j0 + 0], qh[ks], bh0[0], bh0[1]);
                    mmaF(s[j0 + 1], qh[ks], bh0[2], bh0[3]);
                    mmaF(s[j0 + 2], qh[ks], bh1[0], bh1[1]);
                    mmaF(s[j0 + 3], qh[ks], bh1[2], bh1[3]);
                }
            }

            // ---- scale (log2 domain) + causal + padding masks ----
            const unsigned char* pmb = pm + (size_t)b * SEQ + C0;
            const int r0 = Rg + g, r1 = r0 + 8;
            #pragma unroll
            for (int j = 0; j < 8; j++) {
                const int c0 = C0 + 8 * j + 2 * t, c1 = c0 + 1;
                const bool p0 = pmb[8 * j + 2 * t] != 0;
                const bool p1 = pmb[8 * j + 2 * t + 1] != 0;
                float v;
                v = s[j][0] * SCALE_LOG2E; if (c0 > r0 || p0) v = -1e30f; s[j][0] = v;
                v = s[j][1] * SCALE_LOG2E; if (c1 > r0 || p1) v = -1e30f; s[j][1] = v;
                v = s[j][2] * SCALE_LOG2E; if (c0 > r1 || p0) v = -1e30f; s[j][2] = v;
                v = s[j][3] * SCALE_LOG2E; if (c1 > r1 || p1) v = -1e30f; s[j][3] = v;
            }

            // ---- online softmax, base-2, FMA-pipe exp ----
            #pragma unroll
            for (int rr = 0; rr < 2; rr++) {
                float rm = -1e30f;
                #pragma unroll
                for (int j = 0; j < 8; j++)
                    rm = fmaxf(rm, fmaxf(s[j][2 * rr], s[j][2 * rr + 1]));
                rm = fmaxf(rm, __shfl_xor_sync(0xffffffffu, rm, 1));
                rm = fmaxf(rm, __shfl_xor_sync(0xffffffffu, rm, 2));
                const float mn    = fmaxf(m_i[rr], rm);
                const float alpha = exp2_fast(m_i[rr] - mn);
                m_i[rr] = mn;
                float rs = 0.f;
                #pragma unroll
                for (int j = 0; j < 8; j++) {
                    s[j][2 * rr    ] = exp2_fast(s[j][2 * rr    ] - mn);
                    s[j][2 * rr + 1] = exp2_fast(s[j][2 * rr + 1] - mn);
                    rs += s[j][2 * rr] + s[j][2 * rr + 1];
                }
                rs += __shfl_xor_sync(0xffffffffu, rs, 1);
                rs += __shfl_xor_sync(0xffffffffu, rs, 2);
                l_i[rr] = l_i[rr] * alpha + rs;
                #pragma unroll
                for (int j = 0; j < 8; j++) {
                    o[j][2 * rr    ] *= alpha;
                    o[j][2 * rr + 1] *= alpha;
                }
            }

            // ---- write P single (warp-private rows) ----
            #pragma unroll
            for (int j = 0; j < 8; j++) {
                const int p0 = (rw + g) * QSTR + 8 * j + 2 * t;
                const int p1 = p0 + 8 * QSTR;
                *(unsigned*)&Ph[p0] = pk(__float2half_rn(s[j][0]),
                                         __float2half_rn(s[j][1]));
                *(unsigned*)&Ph[p1] = pk(__float2half_rn(s[j][2]),
                                         __float2half_rn(s[j][3]));
            }
            __syncwarp();

            // ---- O += P @ Vh (1-term) ----
            #pragma unroll
            for (int ks = 0; ks < 4; ks++) {
                const int kk = 16 * ks;
                unsigned ph[4];
                ldsm4(ph, Ph + rw * QSTR + kk + aoffQ);
                #pragma unroll
                for (int p = 0; p < 2; p++) {
                    unsigned bh0[4], bh1[4];
                    ldsm4(bh0, Vh + (32 * p     ) * QSTR + kk + boffQ);
                    ldsm4(bh1, Vh + (32 * p + 16) * QSTR + kk + boffQ);
                    const int j0 = 4 * p;
                    mmaF(o[j0 + 0], ph, bh0[0], bh0[1]);
                    mmaF(o[j0 + 1], ph, bh0[2], bh0[3]);
                    mmaF(o[j0 + 2], ph, bh1[0], bh1[1]);
                    mmaF(o[j0 + 3], ph, bh1[2], bh1[3]);
                }
            }
        }
        __syncthreads();
    }

    // ---- normalize + write ctx single [b, s, h*64 + col] ----
    const float inv0 = 1.f / l_i[0];
    const float inv1 = 1.f / l_i[1];
    const int row0 = qt * 128 + rw + g;
    const size_t d0 = ((size_t)b * SEQ + row0    ) * D_MODEL + h * D_HEAD;
    const size_t d1 = ((size_t)b * SEQ + row0 + 8) * D_MODEL + h * D_HEAD;
    #pragma unroll
    for (int j = 0; j < 8; j++) {
        const int cidx = 8 * j + 2 * t;
        *(unsigned*)&g_ch[d0 + cidx] = pk(__float2half_rn(o[j][0] * inv0),
                                          __float2half_rn(o[j][1] * inv0));
        *(unsigned*)&g_ch[d1 + cidx] = pk(__float2half_rn(o[j][2] * inv1),
                                          __float2half_rn(o[j][3] * inv1));
    }
}

// ---------------- launch ----------------------------------------------------
extern "C" void kernel_launch(void* const* d_in, const int* in_sizes, int n_in,
                              void* d_out, int out_size)
{
    (void)in_sizes; (void)n_in; (void)out_size;
    const float* x  = (const float*)d_in[0];
    const float* Qw = (const float*)d_in[1];
    const float* Kw = (const float*)d_in[2];
    const float* Vw = (const float*)d_in[3];
    const float* Ow = (const float*)d_in[4];
    const unsigned char* pm = (const unsigned char*)d_in[5];
    float* out = (float*)d_out;

    cudaFuncSetAttribute(attn_mma, cudaFuncAttributeMaxDynamicSharedMemorySize, ATTN_SMEM);
    cudaFuncSetAttribute(gemm_qkv, cudaFuncAttributeMaxDynamicSharedMemorySize, GEMM_SMEM);
    cudaFuncSetAttribute(gemm_out, cudaFuncAttributeMaxDynamicSharedMemorySize, GEMM_SMEM);

    split_all<<<12288, 256>>>(x, Qw, Kw, Vw, Ow);

    dim3 gq(D_MODEL / 128, MTOT / 128, 3);        // 8 x 64 x 3
    gemm_qkv<<<gq, 128, GEMM_SMEM>>>();

    dim3 ga(SEQ / 128, NUM_HEADS, BATCH);         // 16 x 16 x 4
    attn_mma<<<ga, 256, ATTN_SMEM>>>(pm);

    dim3 go(D_MODEL / 128, MTOT / 128);           // 8 x 64
    gemm_out<<<go, 128, GEMM_SMEM>>>(out);
}